// round 1
// baseline (speedup 1.0000x reference)
#include <cuda_runtime.h>

#define NN 200000
#define EE 600000
#define GG 8192
#define HH 128

// ---------------- scratch (device globals: allocation-free) ----------------
__device__ float g_h  [(size_t)NN*HH];
__device__ float g_hw [(size_t)NN*HH];
__device__ float g_agg[(size_t)NN*HH];
__device__ float g_dis[NN];
__device__ float g_gsum[(size_t)GG*HH];
__device__ float g_cnt[GG];
__device__ float g_gh [(size_t)GG*HH];

__device__ __forceinline__ float4 ld4(const float* p){ return *reinterpret_cast<const float4*>(p); }
__device__ __forceinline__ void  st4(float* p, float4 v){ *reinterpret_cast<float4*>(p) = v; }
__device__ __forceinline__ float siluf(float x){ return x / (1.f + __expf(-x)); }
__device__ __forceinline__ float wredsum(float v){
#pragma unroll
    for (int o = 16; o; o >>= 1) v += __shfl_xor_sync(0xffffffffu, v, o);
    return v;
}

// ---------------- degree / norm ----------------
__global__ void deg_init_k(){
    int i = blockIdx.x*blockDim.x + threadIdx.x;
    if (i < NN) g_dis[i] = 1.0f;           // self-loop contributes 1
}
__global__ void deg_acc_k(const int* __restrict__ dst){
    int e = blockIdx.x*blockDim.x + threadIdx.x;
    if (e < EE) atomicAdd(&g_dis[dst[e]], 1.0f);
}
__global__ void deg_fin_k(){
    int i = blockIdx.x*blockDim.x + threadIdx.x;
    if (i < NN) g_dis[i] = rsqrtf(g_dis[i]);
}

// ---------------- GEMM: out[M,128] = A[M,K] @ W[128,K]^T (+ epilogues) ------
// BM=BN=128, BK=32, 256 threads, 8x8 microtile per thread.
// EPI 0: out = acc (+bias if non-null)
// EPI 1: (conv) out(g_hw)=acc ; g_agg = acc*dis[row]^2 + bias
// EPI 2: out = silu(acc + bias)
// EPI 3: (head) out = silu(acc + bias + g_gh[batch[row]])
template<int KT, int EPI, bool A2F>
__global__ __launch_bounds__(256) void gemm_k(
    const float* __restrict__ A, const float* __restrict__ Ab,
    const float* __restrict__ W, int ldw,
    const float* __restrict__ bias,
    float* __restrict__ out, int M,
    const int* __restrict__ batch)
{
    __shared__ float As[32][129];   // As[k][m]
    __shared__ float Ws[32][132];   // Ws[k][n]
    const int tid  = threadIdx.x;
    const int tr   = tid >> 4;      // 0..15
    const int tc   = tid & 15;      // 0..15
    const int brow = blockIdx.x * 128;

    float acc[8][8];
#pragma unroll
    for (int i = 0; i < 8; i++)
#pragma unroll
        for (int j = 0; j < 8; j++) acc[i][j] = 0.f;

    const int lrow = tid >> 3;        // 0..31
    const int lk   = (tid & 7) * 4;   // 0,4,...,28

    for (int k0 = 0; k0 < KT; k0 += 32) {
        // A tile (transposed into smem)
#pragma unroll
        for (int rr = 0; rr < 4; rr++) {
            int r  = lrow + rr*32;
            int gr = brow + r;
            float4 v = make_float4(0.f,0.f,0.f,0.f);
            if (gr < M) {
                v = ld4(A + (size_t)gr*KT + k0 + lk);
                if (A2F) {
                    float4 u = ld4(Ab + (size_t)gr*KT + k0 + lk);
                    v.x += u.x; v.y += u.y; v.z += u.z; v.w += u.w;
                }
            }
            As[lk+0][r] = v.x; As[lk+1][r] = v.y; As[lk+2][r] = v.z; As[lk+3][r] = v.w;
        }
        // W tile (transposed into smem); W row n has stride ldw
#pragma unroll
        for (int rr = 0; rr < 4; rr++) {
            int n = lrow + rr*32;
            float4 v = ld4(W + (size_t)n*ldw + k0 + lk);
            Ws[lk+0][n] = v.x; Ws[lk+1][n] = v.y; Ws[lk+2][n] = v.z; Ws[lk+3][n] = v.w;
        }
        __syncthreads();
#pragma unroll
        for (int kk = 0; kk < 32; kk++) {
            float a[8];
#pragma unroll
            for (int i = 0; i < 8; i++) a[i] = As[kk][tr*8 + i];
            float4 w0 = *reinterpret_cast<const float4*>(&Ws[kk][tc*8]);
            float4 w1 = *reinterpret_cast<const float4*>(&Ws[kk][tc*8+4]);
            float w[8] = {w0.x,w0.y,w0.z,w0.w,w1.x,w1.y,w1.z,w1.w};
#pragma unroll
            for (int i = 0; i < 8; i++)
#pragma unroll
                for (int j = 0; j < 8; j++)
                    acc[i][j] = fmaf(a[i], w[j], acc[i][j]);
        }
        __syncthreads();
    }

    const int col0 = tc*8;
#pragma unroll
    for (int i = 0; i < 8; i++) {
        int row = brow + tr*8 + i;
        if (row >= M) break;
        size_t o = (size_t)row*HH + col0;
        if (EPI == 1) {
            float dv = g_dis[row];
            float sn = dv*dv;
#pragma unroll
            for (int j = 0; j < 8; j++) {
                float hwv = acc[i][j];
                out[o+j]   = hwv;
                g_agg[o+j] = fmaf(hwv, sn, bias[col0+j]);
            }
        } else {
            const float* ghrow = (EPI == 3) ? (g_gh + (size_t)batch[row]*HH) : nullptr;
#pragma unroll
            for (int j = 0; j < 8; j++) {
                float v = acc[i][j];
                if (bias) v += bias[col0+j];
                if (EPI == 3) v += ghrow[col0+j];
                if (EPI == 2 || EPI == 3) v = siluf(v);
                out[o+j] = v;
            }
        }
    }
}

// ---------------- edge scatter: agg[dst] += hw[src] * dis[src]*dis[dst] ----
__global__ __launch_bounds__(256) void scatter_k(const int* __restrict__ src,
                                                 const int* __restrict__ dst)
{
    int e = blockIdx.x * (blockDim.x >> 5) + (threadIdx.x >> 5);
    if (e >= EE) return;
    int lane = threadIdx.x & 31;
    int s = src[e], d = dst[e];
    float w = g_dis[s] * g_dis[d];
    float4 v = ld4(g_hw + (size_t)s*HH + lane*4);
    float* p = g_agg + (size_t)d*HH + lane*4;
    atomicAdd(p+0, v.x*w);
    atomicAdd(p+1, v.y*w);
    atomicAdd(p+2, v.z*w);
    atomicAdd(p+3, v.w*w);
}

// ---------------- h += LayerNorm(silu(agg)) * g + b ------------------------
__global__ __launch_bounds__(256) void silu_ln_res_k(const float* __restrict__ lng,
                                                     const float* __restrict__ lnb)
{
    int row = blockIdx.x * (blockDim.x >> 5) + (threadIdx.x >> 5);
    if (row >= NN) return;
    int lane = threadIdx.x & 31;
    size_t off = (size_t)row*HH + lane*4;
    float4 a = ld4(g_agg + off);
    float s0 = siluf(a.x), s1 = siluf(a.y), s2 = siluf(a.z), s3 = siluf(a.w);
    float sum = wredsum(s0+s1+s2+s3);
    float sq  = wredsum(s0*s0 + s1*s1 + s2*s2 + s3*s3);
    float mu  = sum * (1.f/128.f);
    float var = sq * (1.f/128.f) - mu*mu;
    float inv = rsqrtf(var + 1e-5f);
    float4 h = ld4(g_h + off);
    int c = lane*4;
    h.x += (s0 - mu)*inv*lng[c+0] + lnb[c+0];
    h.y += (s1 - mu)*inv*lng[c+1] + lnb[c+1];
    h.z += (s2 - mu)*inv*lng[c+2] + lnb[c+2];
    h.w += (s3 - mu)*inv*lng[c+3] + lnb[c+3];
    st4(g_h + off, h);
}

// ---------------- global mean pool ----------------
__global__ void zero_pool_k(){
    int i = blockIdx.x*blockDim.x + threadIdx.x;
    if (i < GG*HH) g_gsum[i] = 0.f;
    if (i < GG)    g_cnt[i]  = 0.f;
}
__global__ __launch_bounds__(256) void pool_k(const int* __restrict__ batch){
    int row = blockIdx.x * (blockDim.x >> 5) + (threadIdx.x >> 5);
    if (row >= NN) return;
    int lane = threadIdx.x & 31;
    int b = batch[row];
    float4 v = ld4(g_h + (size_t)row*HH + lane*4);
    float* p = g_gsum + (size_t)b*HH + lane*4;
    atomicAdd(p+0, v.x);
    atomicAdd(p+1, v.y);
    atomicAdd(p+2, v.z);
    atomicAdd(p+3, v.w);
    if (lane == 0) atomicAdd(&g_cnt[b], 1.0f);
}
__global__ void pool_fin_k(){
    int i = blockIdx.x*blockDim.x + threadIdx.x;
    if (i < GG*HH) {
        int g = i / HH;
        g_gsum[i] = g_gsum[i] / fmaxf(g_cnt[g], 1.0f);
    }
}

// ---------------- final dot: out[n] = hid[n] . w2 + b2 ---------------------
__global__ __launch_bounds__(256) void dot_k(const float* __restrict__ w2,
                                             const float* __restrict__ b2,
                                             float* __restrict__ out)
{
    int row = blockIdx.x * (blockDim.x >> 5) + (threadIdx.x >> 5);
    if (row >= NN) return;
    int lane = threadIdx.x & 31;
    float4 v = ld4(g_hw + (size_t)row*HH + lane*4);
    float4 w = ld4(w2 + lane*4);
    float sum = wredsum(v.x*w.x + v.y*w.y + v.z*w.z + v.w*w.w);
    if (lane == 0) out[row] = sum + b2[0];
}

// ---------------- launch ----------------
extern "C" void kernel_launch(void* const* d_in, const int* in_sizes, int n_in,
                              void* d_out, int out_size)
{
    const float* x      = (const float*)d_in[0];
    const int*   ei     = (const int*)  d_in[1];
    const int*   src    = ei;
    const int*   dst    = ei + EE;
    const int*   batch  = (const int*)  d_in[2];
    const float* in_w   = (const float*)d_in[3];
    const float* in_b   = (const float*)d_in[4];
    const float* conv_w = (const float*)d_in[5];
    const float* conv_b = (const float*)d_in[6];
    const float* ln_g   = (const float*)d_in[7];
    const float* ln_b   = (const float*)d_in[8];
    const float* pw1    = (const float*)d_in[9];
    const float* pb1    = (const float*)d_in[10];
    const float* pw2    = (const float*)d_in[11];
    const float* pb2    = (const float*)d_in[12];
    const float* hw1    = (const float*)d_in[13];
    const float* hb1    = (const float*)d_in[14];
    const float* hw2    = (const float*)d_in[15];
    const float* hb2    = (const float*)d_in[16];
    float* out = (float*)d_out;

    float *p_h, *p_hw, *p_agg, *p_gsum, *p_gh;
    cudaGetSymbolAddress((void**)&p_h,    g_h);
    cudaGetSymbolAddress((void**)&p_hw,   g_hw);
    cudaGetSymbolAddress((void**)&p_agg,  g_agg);
    cudaGetSymbolAddress((void**)&p_gsum, g_gsum);
    cudaGetSymbolAddress((void**)&p_gh,   g_gh);

    const int TPB = 256;
    const int gN   = (NN + TPB - 1) / TPB;
    const int gE   = (EE + TPB - 1) / TPB;
    const int gWN  = (NN + 7) / 8;      // warp-per-row
    const int gWE  = (EE + 7) / 8;      // warp-per-edge
    const int gGm  = (NN + 127) / 128;  // gemm over nodes
    const int gGg  = (GG + 127) / 128;  // gemm over graphs
    const int gGH  = (GG*HH + TPB - 1) / TPB;

    // degree -> dis
    deg_init_k<<<gN, TPB>>>();
    deg_acc_k <<<gE, TPB>>>(dst);
    deg_fin_k <<<gN, TPB>>>();

    // input projection: h = x @ in_w.T + in_b
    gemm_k<64, 0, false><<<gGm, TPB>>>(x, nullptr, in_w, 64, in_b, p_h, NN, nullptr);

    // GCN layers
    for (int l = 0; l < 4; l++) {
        gemm_k<128, 1, false><<<gGm, TPB>>>(p_h, nullptr, conv_w + (size_t)l*HH*HH, 128,
                                            conv_b + l*HH, p_hw, NN, nullptr);
        scatter_k<<<gWE, TPB>>>(src, dst);
        silu_ln_res_k<<<gWN, TPB>>>(ln_g + l*HH, ln_b + l*HH);
    }

    // global mean pool -> per-graph head contribution gh = graph_emb @ W1b.T
    zero_pool_k<<<gGH, TPB>>>();
    pool_k     <<<gWN, TPB>>>(batch);
    pool_fin_k <<<gGH, TPB>>>();
    gemm_k<128, 0, false><<<gGg, TPB>>>(p_gsum, nullptr, hw1 + 128, 256, nullptr,
                                        p_gh, GG, nullptr);

    // physics MLP: t1 = silu(h@pw1.T+pb1) ; phys = t1@pw2.T+pb2
    gemm_k<128, 2, false><<<gGm, TPB>>>(p_h,  nullptr, pw1, 128, pb1, p_hw,  NN, nullptr);
    gemm_k<128, 0, false><<<gGm, TPB>>>(p_hw, nullptr, pw2, 128, pb2, p_agg, NN, nullptr);

    // head: hid = silu((h+phys)@W1a.T + gh[batch] + b1) ; out = hid.w2 + b2
    gemm_k<128, 3, true><<<gGm, TPB>>>(p_h, p_agg, hw1, 256, hb1, p_hw, NN, batch);
    dot_k<<<gWN, TPB>>>(hw2, hb2, out);
}

// round 4
// speedup vs baseline: 2.1687x; 2.1687x over previous
#include <cuda_runtime.h>
#include <cstdint>

#define NN 200000
#define EE 600000
#define GG 8192
#define HH 128

// ---------------- scratch (device globals: allocation-free) ----------------
__device__ float g_h  [(size_t)NN*HH];
__device__ float g_hw [(size_t)NN*HH];
__device__ float g_agg[(size_t)NN*HH];
__device__ float g_dis[NN];
__device__ float g_gsum[(size_t)GG*HH];
__device__ float g_cnt[GG];
__device__ float g_gh [(size_t)GG*HH];

// ---------------- small helpers ----------------
__device__ __forceinline__ float4 ld4(const float* p){ return *reinterpret_cast<const float4*>(p); }
__device__ __forceinline__ void  st4(float* p, float4 v){ *reinterpret_cast<float4*>(p) = v; }
__device__ __forceinline__ void  st2(float* p, float a, float b){
    *reinterpret_cast<float2*>(p) = make_float2(a, b);
}
__device__ __forceinline__ float siluf(float x){ return x / (1.f + __expf(-x)); }
__device__ __forceinline__ float wredsum(float v){
#pragma unroll
    for (int o = 16; o; o >>= 1) v += __shfl_xor_sync(0xffffffffu, v, o);
    return v;
}
__device__ __forceinline__ uint32_t f2tf32(float f){
    uint32_t u;
    asm("cvt.rna.tf32.f32 %0, %1;" : "=r"(u) : "f"(f));
    return u;
}

// m16n8k8 tf32 MMA (sm_80+ PTX; HMMA on Blackwell)
__device__ __forceinline__ void mma1688(float* d, const uint32_t* a, const uint32_t* b){
    asm volatile("mma.sync.aligned.m16n8k8.row.col.f32.tf32.tf32.f32 "
        "{%0,%1,%2,%3}, {%4,%5,%6,%7}, {%8,%9}, {%0,%1,%2,%3};"
        : "+f"(d[0]), "+f"(d[1]), "+f"(d[2]), "+f"(d[3])
        : "r"(a[0]), "r"(a[1]), "r"(a[2]), "r"(a[3]), "r"(b[0]), "r"(b[1]));
}

// ---------------- degree / norm ----------------
__global__ void deg_init_k(){
    int i = blockIdx.x*blockDim.x + threadIdx.x;
    if (i < NN) g_dis[i] = 1.0f;
}
__global__ void deg_acc_k(const int* __restrict__ dst){
    int e = blockIdx.x*blockDim.x + threadIdx.x;
    if (e < EE) atomicAdd(&g_dis[dst[e]], 1.0f);
}
__global__ void deg_fin_k(){
    int i = blockIdx.x*blockDim.x + threadIdx.x;
    if (i < NN) g_dis[i] = rsqrtf(g_dis[i]);
}

// ---------------- TF32 tensor-core GEMM -------------------------------------
// out[M,128] = A[M,KT] @ W[128,KT]^T   (W rows have stride ldw)
// EPI 0: out = acc (+bias if non-null)
// EPI 1: (conv) out(g_hw)=acc ; g_agg = acc*dis[row]^2 + bias
// EPI 2: out = silu(acc + bias)
// EPI 3: (head) out = silu(acc + bias + g_gh[batch[row]])
// 256 threads = 8 warps, warp grid 4(M)x2(N): warp tile 32x64.
// K processed in chunks of 64 held in padded SMEM (stride 68 floats).
template<int KT, int EPI, bool A2F>
__global__ __launch_bounds__(256, 2) void mma_gemm_k(
    const float* __restrict__ A, const float* __restrict__ Ab,
    const float* __restrict__ W, int ldw, const float* __restrict__ bias,
    float* __restrict__ out, int M, const int* __restrict__ batch)
{
    constexpr int KC  = 64;
    constexpr int LDSN = KC + 4;           // 68 floats
    extern __shared__ float smem[];
    float* As = smem;                       // [128][68]
    float* Ws = smem + 128*LDSN;            // [128][68]

    const int tid = threadIdx.x, wid = tid >> 5, lid = tid & 31;
    const int wm = wid & 3, wn = wid >> 2;
    const int g  = lid >> 2, t = lid & 3;
    const int brow = blockIdx.x * 128;

    float acc[2][8][4];
#pragma unroll
    for (int mt = 0; mt < 2; mt++)
#pragma unroll
        for (int nt = 0; nt < 8; nt++)
#pragma unroll
            for (int q = 0; q < 4; q++) acc[mt][nt][q] = 0.f;

    for (int k0 = 0; k0 < KT; k0 += KC) {
        if (k0) __syncthreads();
        // A chunk: 128 rows x 64 cols (float4 per thread iteration)
#pragma unroll
        for (int f = tid; f < 128*16; f += 256) {
            int row = f >> 4, kq = (f & 15) * 4;
            int gr = brow + row;
            float4 v = make_float4(0.f,0.f,0.f,0.f);
            if (gr < M) {
                v = ld4(A + (size_t)gr*KT + k0 + kq);
                if (A2F) { float4 u = ld4(Ab + (size_t)gr*KT + k0 + kq);
                           v.x += u.x; v.y += u.y; v.z += u.z; v.w += u.w; }
            }
            uint4 c = make_uint4(f2tf32(v.x), f2tf32(v.y), f2tf32(v.z), f2tf32(v.w));
            *reinterpret_cast<uint4*>(As + row*LDSN + kq) = c;
        }
        // W chunk
#pragma unroll
        for (int f = tid; f < 128*16; f += 256) {
            int n = f >> 4, kq = (f & 15) * 4;
            float4 v = ld4(W + (size_t)n*ldw + k0 + kq);
            uint4 c = make_uint4(f2tf32(v.x), f2tf32(v.y), f2tf32(v.z), f2tf32(v.w));
            *reinterpret_cast<uint4*>(Ws + n*LDSN + kq) = c;
        }
        __syncthreads();

#pragma unroll
        for (int ks = 0; ks < KC/8; ks++) {
            const int kk = ks*8;
            uint32_t a[2][4], b[8][2];
#pragma unroll
            for (int mt = 0; mt < 2; mt++) {
                const float* ap = As + (wm*32 + mt*16 + g)*LDSN + kk + t;
                a[mt][0] = __float_as_uint(ap[0]);
                a[mt][1] = __float_as_uint(ap[8*LDSN]);
                a[mt][2] = __float_as_uint(ap[4]);
                a[mt][3] = __float_as_uint(ap[8*LDSN + 4]);
            }
#pragma unroll
            for (int nt = 0; nt < 8; nt++) {
                const float* bp = Ws + (wn*64 + nt*8 + g)*LDSN + kk + t;
                b[nt][0] = __float_as_uint(bp[0]);
                b[nt][1] = __float_as_uint(bp[4]);
            }
#pragma unroll
            for (int mt = 0; mt < 2; mt++)
#pragma unroll
                for (int nt = 0; nt < 8; nt++)
                    mma1688(acc[mt][nt], a[mt], b[nt]);
        }
    }

    // ---- epilogue: fragment layout c0:(g,2t) c1:(g,2t+1) c2:(g+8,2t) c3:(g+8,2t+1)
#pragma unroll
    for (int mt = 0; mt < 2; mt++) {
#pragma unroll
        for (int half = 0; half < 2; half++) {
            int row = brow + wm*32 + mt*16 + g + half*8;
            if (row >= M) continue;
            float sn = 0.f;
            const float* ghrow = nullptr;
            if (EPI == 1) { float dv = g_dis[row]; sn = dv*dv; }
            if (EPI == 3) { ghrow = g_gh + (size_t)batch[row]*HH; }
            size_t ro = (size_t)row*HH;
#pragma unroll
            for (int nt = 0; nt < 8; nt++) {
                int col = wn*64 + nt*8 + t*2;
                float v0 = acc[mt][nt][half*2 + 0];
                float v1 = acc[mt][nt][half*2 + 1];
                if (EPI == 1) {
                    st2(g_hw + ro + col, v0, v1);
                    float b0 = bias[col], b1 = bias[col+1];
                    st2(g_agg + ro + col, fmaf(v0, sn, b0), fmaf(v1, sn, b1));
                } else {
                    if (EPI == 0) {
                        if (bias) { v0 += bias[col]; v1 += bias[col+1]; }
                    } else if (EPI == 2) {
                        v0 = siluf(v0 + bias[col]); v1 = siluf(v1 + bias[col+1]);
                    } else if (EPI == 3) {
                        v0 = siluf(v0 + bias[col]   + ghrow[col]);
                        v1 = siluf(v1 + bias[col+1] + ghrow[col+1]);
                    }
                    st2(out + ro + col, v0, v1);
                }
            }
        }
    }
}

// ---------------- edge scatter: agg[dst] += hw[src] * dis[src]*dis[dst] ----
__global__ __launch_bounds__(256) void scatter_k(const int* __restrict__ src,
                                                 const int* __restrict__ dst)
{
    int e = blockIdx.x * 8 + (threadIdx.x >> 5);
    if (e >= EE) return;
    int lane = threadIdx.x & 31;
    int s = src[e], d = dst[e];
    float w = g_dis[s] * g_dis[d];
    float4 v = ld4(g_hw + (size_t)s*HH + lane*4);
    float* p = g_agg + (size_t)d*HH + lane*4;
    asm volatile("red.global.add.v4.f32 [%0], {%1,%2,%3,%4};"
                 :: "l"(p), "f"(v.x*w), "f"(v.y*w), "f"(v.z*w), "f"(v.w*w) : "memory");
}

// ---------------- h += LayerNorm(silu(agg)) * g + b ------------------------
__global__ __launch_bounds__(256) void silu_ln_res_k(const float* __restrict__ lng,
                                                     const float* __restrict__ lnb)
{
    int row = blockIdx.x * 8 + (threadIdx.x >> 5);
    if (row >= NN) return;
    int lane = threadIdx.x & 31;
    size_t off = (size_t)row*HH + lane*4;
    float4 a = ld4(g_agg + off);
    float s0 = siluf(a.x), s1 = siluf(a.y), s2 = siluf(a.z), s3 = siluf(a.w);
    float sum = wredsum(s0+s1+s2+s3);
    float sq  = wredsum(s0*s0 + s1*s1 + s2*s2 + s3*s3);
    float mu  = sum * (1.f/128.f);
    float var = sq * (1.f/128.f) - mu*mu;
    float inv = rsqrtf(var + 1e-5f);
    float4 h = ld4(g_h + off);
    int c = lane*4;
    h.x += (s0 - mu)*inv*lng[c+0] + lnb[c+0];
    h.y += (s1 - mu)*inv*lng[c+1] + lnb[c+1];
    h.z += (s2 - mu)*inv*lng[c+2] + lnb[c+2];
    h.w += (s3 - mu)*inv*lng[c+3] + lnb[c+3];
    st4(g_h + off, h);
}

// ---------------- global mean pool ----------------
__global__ void zero_pool_k(){
    int i = blockIdx.x*blockDim.x + threadIdx.x;
    if (i < GG*HH) g_gsum[i] = 0.f;
    if (i < GG)    g_cnt[i]  = 0.f;
}
__global__ __launch_bounds__(256) void pool_k(const int* __restrict__ batch){
    int row = blockIdx.x * 8 + (threadIdx.x >> 5);
    if (row >= NN) return;
    int lane = threadIdx.x & 31;
    int b = batch[row];
    float4 v = ld4(g_h + (size_t)row*HH + lane*4);
    float* p = g_gsum + (size_t)b*HH + lane*4;
    asm volatile("red.global.add.v4.f32 [%0], {%1,%2,%3,%4};"
                 :: "l"(p), "f"(v.x), "f"(v.y), "f"(v.z), "f"(v.w) : "memory");
    if (lane == 0) atomicAdd(&g_cnt[b], 1.0f);
}
__global__ void pool_fin_k(){
    int i = blockIdx.x*blockDim.x + threadIdx.x;
    if (i < GG*HH) {
        int g = i / HH;
        g_gsum[i] = g_gsum[i] / fmaxf(g_cnt[g], 1.0f);
    }
}

// ---------------- final dot: out[n] = hid[n] . w2 + b2 ---------------------
__global__ __launch_bounds__(256) void dot_k(const float* __restrict__ w2,
                                             const float* __restrict__ b2,
                                             float* __restrict__ out)
{
    int row = blockIdx.x * 8 + (threadIdx.x >> 5);
    if (row >= NN) return;
    int lane = threadIdx.x & 31;
    float4 v = ld4(g_hw + (size_t)row*HH + lane*4);
    float4 w = ld4(w2 + lane*4);
    float sum = wredsum(v.x*w.x + v.y*w.y + v.z*w.z + v.w*w.w);
    if (lane == 0) out[row] = sum + b2[0];
}

// ---------------- launch ----------------
extern "C" void kernel_launch(void* const* d_in, const int* in_sizes, int n_in,
                              void* d_out, int out_size)
{
    const float* x      = (const float*)d_in[0];
    const int*   ei     = (const int*)  d_in[1];
    const int*   src    = ei;
    const int*   dst    = ei + EE;
    const int*   batch  = (const int*)  d_in[2];
    const float* in_w   = (const float*)d_in[3];
    const float* in_b   = (const float*)d_in[4];
    const float* conv_w = (const float*)d_in[5];
    const float* conv_b = (const float*)d_in[6];
    const float* ln_g   = (const float*)d_in[7];
    const float* ln_b   = (const float*)d_in[8];
    const float* pw1    = (const float*)d_in[9];
    const float* pb1    = (const float*)d_in[10];
    const float* pw2    = (const float*)d_in[11];
    const float* pb2    = (const float*)d_in[12];
    const float* hw1    = (const float*)d_in[13];
    const float* hb1    = (const float*)d_in[14];
    const float* hw2    = (const float*)d_in[15];
    const float* hb2    = (const float*)d_in[16];
    float* out = (float*)d_out;

    float *p_h, *p_hw, *p_agg, *p_gsum, *p_gh;
    cudaGetSymbolAddress((void**)&p_h,    g_h);
    cudaGetSymbolAddress((void**)&p_hw,   g_hw);
    cudaGetSymbolAddress((void**)&p_agg,  g_agg);
    cudaGetSymbolAddress((void**)&p_gsum, g_gsum);
    cudaGetSymbolAddress((void**)&p_gh,   g_gh);

    const int TPB = 256;
    const int gN  = (NN + TPB - 1) / TPB;
    const int gE  = (EE + TPB - 1) / TPB;
    const int gWN = (NN + 7) / 8;
    const int gWE = (EE + 7) / 8;
    const int gGm = (NN + 127) / 128;
    const int gGg = GG / 128;
    const int gGH = (GG*HH + TPB - 1) / TPB;

    const int SMB = 2 * 128 * 68 * 4;   // 69632 B dynamic smem
    cudaFuncSetAttribute(mma_gemm_k< 64,0,false>, cudaFuncAttributeMaxDynamicSharedMemorySize, SMB);
    cudaFuncSetAttribute(mma_gemm_k<128,0,false>, cudaFuncAttributeMaxDynamicSharedMemorySize, SMB);
    cudaFuncSetAttribute(mma_gemm_k<128,1,false>, cudaFuncAttributeMaxDynamicSharedMemorySize, SMB);
    cudaFuncSetAttribute(mma_gemm_k<128,2,false>, cudaFuncAttributeMaxDynamicSharedMemorySize, SMB);
    cudaFuncSetAttribute(mma_gemm_k<128,3,true >, cudaFuncAttributeMaxDynamicSharedMemorySize, SMB);

    // degree -> dis
    deg_init_k<<<gN, TPB>>>();
    deg_acc_k <<<gE, TPB>>>(dst);
    deg_fin_k <<<gN, TPB>>>();

    // input projection: h = x @ in_w.T + in_b
    mma_gemm_k<64,0,false><<<gGm, TPB, SMB>>>(x, nullptr, in_w, 64, in_b, p_h, NN, nullptr);

    // GCN layers
    for (int l = 0; l < 4; l++) {
        mma_gemm_k<128,1,false><<<gGm, TPB, SMB>>>(p_h, nullptr, conv_w + (size_t)l*HH*HH, 128,
                                                   conv_b + l*HH, p_hw, NN, nullptr);
        scatter_k<<<gWE, TPB>>>(src, dst);
        silu_ln_res_k<<<gWN, TPB>>>(ln_g + l*HH, ln_b + l*HH);
    }

    // global mean pool -> per-graph head contribution gh = graph_emb @ W1b.T
    zero_pool_k<<<gGH, TPB>>>();
    pool_k     <<<gWN, TPB>>>(batch);
    pool_fin_k <<<gGH, TPB>>>();
    mma_gemm_k<128,0,false><<<gGg, TPB, SMB>>>(p_gsum, nullptr, hw1 + 128, 256, nullptr,
                                               p_gh, GG, nullptr);

    // physics MLP: t1 = silu(h@pw1.T+pb1) ; phys = t1@pw2.T+pb2
    mma_gemm_k<128,2,false><<<gGm, TPB, SMB>>>(p_h,  nullptr, pw1, 128, pb1, p_hw,  NN, nullptr);
    mma_gemm_k<128,0,false><<<gGm, TPB, SMB>>>(p_hw, nullptr, pw2, 128, pb2, p_agg, NN, nullptr);

    // head: hid = silu((h+phys)@W1a.T + gh[batch] + b1) ; out = hid.w2 + b2
    mma_gemm_k<128,3,true><<<gGm, TPB, SMB>>>(p_h, p_agg, hw1, 256, hb1, p_hw, NN, batch);
    dot_k<<<gWN, TPB>>>(hw2, hb2, out);
}

// round 5
// speedup vs baseline: 2.8453x; 1.3120x over previous
#include <cuda_runtime.h>
#include <cstdint>

#define NN 200000
#define EE 600000
#define GG 8192
#define HH 128
#define NB 196            // scan blocks: 196*1024 >= NN

// ---------------- scratch (device globals: allocation-free) ----------------
__device__ float g_h  [(size_t)NN*HH];
__device__ float g_hw [(size_t)NN*HH];
__device__ float g_tmp[(size_t)NN*HH];
__device__ float g_dis[NN];
__device__ float g_gsum[(size_t)GG*HH];
__device__ float g_cnt[GG];
__device__ float g_gh [(size_t)GG*HH];
// CSR
__device__ int g_deg[NN];
__device__ int g_fill[NN];
__device__ int g_rowptr[NN];
__device__ int g_csrc[EE];
__device__ int g_bsum[256];
__device__ int g_boff[256];

// ---------------- small helpers ----------------
__device__ __forceinline__ float4 ld4(const float* p){ return *reinterpret_cast<const float4*>(p); }
__device__ __forceinline__ void  st4(float* p, float4 v){ *reinterpret_cast<float4*>(p) = v; }
__device__ __forceinline__ void  st2(float* p, float a, float b){
    *reinterpret_cast<float2*>(p) = make_float2(a, b);
}
__device__ __forceinline__ float siluf(float x){ return x / (1.f + __expf(-x)); }
__device__ __forceinline__ float wredsum(float v){
#pragma unroll
    for (int o = 16; o; o >>= 1) v += __shfl_xor_sync(0xffffffffu, v, o);
    return v;
}
__device__ __forceinline__ uint32_t f2tf32(float f){
    uint32_t u;
    asm("cvt.rna.tf32.f32 %0, %1;" : "=r"(u) : "f"(f));
    return u;
}
__device__ __forceinline__ void mma1688(float* d, const uint32_t* a, const uint32_t* b){
    asm volatile("mma.sync.aligned.m16n8k8.row.col.f32.tf32.tf32.f32 "
        "{%0,%1,%2,%3}, {%4,%5,%6,%7}, {%8,%9}, {%0,%1,%2,%3};"
        : "+f"(d[0]), "+f"(d[1]), "+f"(d[2]), "+f"(d[3])
        : "r"(a[0]), "r"(a[1]), "r"(a[2]), "r"(a[3]), "r"(b[0]), "r"(b[1]));
}

// ---------------- CSR build ----------------
__global__ void csr_zero_k(){
    int i = blockIdx.x*blockDim.x + threadIdx.x;
    if (i < NN) { g_deg[i] = 0; g_fill[i] = 0; }
}
__global__ void csr_hist_k(const int* __restrict__ dst){
    int e = blockIdx.x*blockDim.x + threadIdx.x;
    if (e < EE) atomicAdd(&g_deg[dst[e]], 1);
}
__global__ __launch_bounds__(256) void csr_scan1_k(){
    __shared__ int ss[256];
    const int tid = threadIdx.x;
    const int i0  = blockIdx.x*1024 + tid*4;
    int v[4];
#pragma unroll
    for (int q = 0; q < 4; q++) v[q] = (i0+q < NN) ? g_deg[i0+q] : 0;
    int tsum = v[0]+v[1]+v[2]+v[3];
    ss[tid] = tsum; __syncthreads();
#pragma unroll
    for (int off = 1; off < 256; off <<= 1) {
        int t = (tid >= off) ? ss[tid-off] : 0;
        __syncthreads();
        ss[tid] += t;
        __syncthreads();
    }
    if (tid == 255) g_bsum[blockIdx.x] = ss[255];
    int run = ss[tid] - tsum;
#pragma unroll
    for (int q = 0; q < 4; q++) {
        if (i0+q < NN) { g_rowptr[i0+q] = run; run += v[q]; }
    }
}
__global__ __launch_bounds__(256) void csr_scan2_k(){
    __shared__ int ss[256];
    const int tid = threadIdx.x;
    int v = (tid < NB) ? g_bsum[tid] : 0;
    ss[tid] = v; __syncthreads();
#pragma unroll
    for (int off = 1; off < 256; off <<= 1) {
        int t = (tid >= off) ? ss[tid-off] : 0;
        __syncthreads();
        ss[tid] += t;
        __syncthreads();
    }
    if (tid < NB) g_boff[tid] = ss[tid] - v;   // exclusive
}
__global__ void csr_scan3_k(){
    int i = blockIdx.x*blockDim.x + threadIdx.x;
    if (i < NN) {
        g_rowptr[i] += g_boff[i >> 10];
        g_dis[i] = rsqrtf((float)g_deg[i] + 1.0f);
    }
}
__global__ void csr_fill_k(const int* __restrict__ src, const int* __restrict__ dst){
    int e = blockIdx.x*blockDim.x + threadIdx.x;
    if (e < EE) {
        int d = dst[e];
        int pos = g_rowptr[d] + atomicAdd(&g_fill[d], 1);
        g_csrc[pos] = src[e];
    }
}

// ---------------- TF32 tensor-core GEMM -------------------------------------
// out[M,128] = A[M,KT] @ W[128,KT]^T   (W rows have stride ldw)
// EPI 0: out = acc (+bias if non-null)
// EPI 2: out = silu(acc + bias)
// EPI 3: (head) out = silu(acc + bias + g_gh[batch[row]])
template<int KT, int EPI, bool A2F>
__global__ __launch_bounds__(256, 2) void mma_gemm_k(
    const float* __restrict__ A, const float* __restrict__ Ab,
    const float* __restrict__ W, int ldw, const float* __restrict__ bias,
    float* __restrict__ out, int M, const int* __restrict__ batch)
{
    constexpr int KC  = 64;
    constexpr int LDSN = KC + 4;           // 68 floats
    extern __shared__ float smem[];
    float* As = smem;                       // [128][68]
    float* Ws = smem + 128*LDSN;            // [128][68]

    const int tid = threadIdx.x, wid = tid >> 5, lid = tid & 31;
    const int wm = wid & 3, wn = wid >> 2;
    const int g  = lid >> 2, t = lid & 3;
    const int brow = blockIdx.x * 128;

    float acc[2][8][4];
#pragma unroll
    for (int mt = 0; mt < 2; mt++)
#pragma unroll
        for (int nt = 0; nt < 8; nt++)
#pragma unroll
            for (int q = 0; q < 4; q++) acc[mt][nt][q] = 0.f;

    for (int k0 = 0; k0 < KT; k0 += KC) {
        if (k0) __syncthreads();
#pragma unroll
        for (int f = tid; f < 128*16; f += 256) {
            int row = f >> 4, kq = (f & 15) * 4;
            int gr = brow + row;
            float4 v = make_float4(0.f,0.f,0.f,0.f);
            if (gr < M) {
                v = ld4(A + (size_t)gr*KT + k0 + kq);
                if (A2F) { float4 u = ld4(Ab + (size_t)gr*KT + k0 + kq);
                           v.x += u.x; v.y += u.y; v.z += u.z; v.w += u.w; }
            }
            uint4 c = make_uint4(f2tf32(v.x), f2tf32(v.y), f2tf32(v.z), f2tf32(v.w));
            *reinterpret_cast<uint4*>(As + row*LDSN + kq) = c;
        }
#pragma unroll
        for (int f = tid; f < 128*16; f += 256) {
            int n = f >> 4, kq = (f & 15) * 4;
            float4 v = ld4(W + (size_t)n*ldw + k0 + kq);
            uint4 c = make_uint4(f2tf32(v.x), f2tf32(v.y), f2tf32(v.z), f2tf32(v.w));
            *reinterpret_cast<uint4*>(Ws + n*LDSN + kq) = c;
        }
        __syncthreads();

#pragma unroll
        for (int ks = 0; ks < KC/8; ks++) {
            const int kk = ks*8;
            uint32_t a[2][4], b[8][2];
#pragma unroll
            for (int mt = 0; mt < 2; mt++) {
                const float* ap = As + (wm*32 + mt*16 + g)*LDSN + kk + t;
                a[mt][0] = __float_as_uint(ap[0]);
                a[mt][1] = __float_as_uint(ap[8*LDSN]);
                a[mt][2] = __float_as_uint(ap[4]);
                a[mt][3] = __float_as_uint(ap[8*LDSN + 4]);
            }
#pragma unroll
            for (int nt = 0; nt < 8; nt++) {
                const float* bp = Ws + (wn*64 + nt*8 + g)*LDSN + kk + t;
                b[nt][0] = __float_as_uint(bp[0]);
                b[nt][1] = __float_as_uint(bp[4]);
            }
#pragma unroll
            for (int mt = 0; mt < 2; mt++)
#pragma unroll
                for (int nt = 0; nt < 8; nt++)
                    mma1688(acc[mt][nt], a[mt], b[nt]);
        }
    }

#pragma unroll
    for (int mt = 0; mt < 2; mt++) {
#pragma unroll
        for (int half = 0; half < 2; half++) {
            int row = brow + wm*32 + mt*16 + g + half*8;
            if (row >= M) continue;
            const float* ghrow = nullptr;
            if (EPI == 3) ghrow = g_gh + (size_t)batch[row]*HH;
            size_t ro = (size_t)row*HH;
#pragma unroll
            for (int nt = 0; nt < 8; nt++) {
                int col = wn*64 + nt*8 + t*2;
                float v0 = acc[mt][nt][half*2 + 0];
                float v1 = acc[mt][nt][half*2 + 1];
                if (EPI == 0) {
                    if (bias) { v0 += bias[col]; v1 += bias[col+1]; }
                } else if (EPI == 2) {
                    v0 = siluf(v0 + bias[col]); v1 = siluf(v1 + bias[col+1]);
                } else if (EPI == 3) {
                    v0 = siluf(v0 + bias[col]   + ghrow[col]);
                    v1 = siluf(v1 + bias[col+1] + ghrow[col+1]);
                }
                st2(out + ro + col, v0, v1);
            }
        }
    }
}

// ---- fused neighbor-gather + self-loop + bias + silu + LayerNorm + residual ----
// warp per dst node; in-edges from CSR; hw rows mostly L2-resident.
__global__ __launch_bounds__(256) void gather_ln_k(const float* __restrict__ bias,
                                                   const float* __restrict__ lng,
                                                   const float* __restrict__ lnb)
{
    int row = blockIdx.x * 8 + (threadIdx.x >> 5);
    if (row >= NN) return;
    int lane = threadIdx.x & 31;
    const int cnt   = g_deg[row];
    const int start = g_rowptr[row];
    const float di  = g_dis[row];
    size_t off = (size_t)row*HH + lane*4;

    // self-loop term + bias
    float4 a  = ld4(g_hw + off);
    float4 b4 = ld4(bias + lane*4);
    float sn  = di * di;
    float ax = fmaf(a.x, sn, b4.x), ay = fmaf(a.y, sn, b4.y);
    float az = fmaf(a.z, sn, b4.z), aw = fmaf(a.w, sn, b4.w);

    for (int j = 0; j < cnt; j++) {
        int s   = g_csrc[start + j];
        float w = g_dis[s] * di;
        float4 v = ld4(g_hw + (size_t)s*HH + lane*4);
        ax = fmaf(v.x, w, ax); ay = fmaf(v.y, w, ay);
        az = fmaf(v.z, w, az); aw = fmaf(v.w, w, aw);
    }

    float s0 = siluf(ax), s1 = siluf(ay), s2 = siluf(az), s3 = siluf(aw);
    float sum = wredsum(s0+s1+s2+s3);
    float sq  = wredsum(s0*s0 + s1*s1 + s2*s2 + s3*s3);
    float mu  = sum * (1.f/128.f);
    float var = sq * (1.f/128.f) - mu*mu;
    float inv = rsqrtf(var + 1e-5f);
    float4 h = ld4(g_h + off);
    int c = lane*4;
    h.x += (s0 - mu)*inv*lng[c+0] + lnb[c+0];
    h.y += (s1 - mu)*inv*lng[c+1] + lnb[c+1];
    h.z += (s2 - mu)*inv*lng[c+2] + lnb[c+2];
    h.w += (s3 - mu)*inv*lng[c+3] + lnb[c+3];
    st4(g_h + off, h);
}

// ---------------- global mean pool ----------------
__global__ void zero_pool_k(){
    int i = blockIdx.x*blockDim.x + threadIdx.x;
    if (i < GG*HH) g_gsum[i] = 0.f;
    if (i < GG)    g_cnt[i]  = 0.f;
}
__global__ __launch_bounds__(256) void pool_k(const int* __restrict__ batch){
    int row = blockIdx.x * 8 + (threadIdx.x >> 5);
    if (row >= NN) return;
    int lane = threadIdx.x & 31;
    int b = batch[row];
    float4 v = ld4(g_h + (size_t)row*HH + lane*4);
    float* p = g_gsum + (size_t)b*HH + lane*4;
    asm volatile("red.global.add.v4.f32 [%0], {%1,%2,%3,%4};"
                 :: "l"(p), "f"(v.x), "f"(v.y), "f"(v.z), "f"(v.w) : "memory");
    if (lane == 0) atomicAdd(&g_cnt[b], 1.0f);
}
__global__ void pool_fin_k(){
    int i = blockIdx.x*blockDim.x + threadIdx.x;
    if (i < GG*HH) {
        int g = i / HH;
        g_gsum[i] = g_gsum[i] / fmaxf(g_cnt[g], 1.0f);
    }
}

// ---------------- final dot: out[n] = hid[n] . w2 + b2 ---------------------
__global__ __launch_bounds__(256) void dot_k(const float* __restrict__ w2,
                                             const float* __restrict__ b2,
                                             float* __restrict__ out)
{
    int row = blockIdx.x * 8 + (threadIdx.x >> 5);
    if (row >= NN) return;
    int lane = threadIdx.x & 31;
    float4 v = ld4(g_hw + (size_t)row*HH + lane*4);
    float4 w = ld4(w2 + lane*4);
    float sum = wredsum(v.x*w.x + v.y*w.y + v.z*w.z + v.w*w.w);
    if (lane == 0) out[row] = sum + b2[0];
}

// ---------------- launch ----------------
extern "C" void kernel_launch(void* const* d_in, const int* in_sizes, int n_in,
                              void* d_out, int out_size)
{
    const float* x      = (const float*)d_in[0];
    const int*   ei     = (const int*)  d_in[1];
    const int*   src    = ei;
    const int*   dst    = ei + EE;
    const int*   batch  = (const int*)  d_in[2];
    const float* in_w   = (const float*)d_in[3];
    const float* in_b   = (const float*)d_in[4];
    const float* conv_w = (const float*)d_in[5];
    const float* conv_b = (const float*)d_in[6];
    const float* ln_g   = (const float*)d_in[7];
    const float* ln_b   = (const float*)d_in[8];
    const float* pw1    = (const float*)d_in[9];
    const float* pb1    = (const float*)d_in[10];
    const float* pw2    = (const float*)d_in[11];
    const float* pb2    = (const float*)d_in[12];
    const float* hw1    = (const float*)d_in[13];
    const float* hb1    = (const float*)d_in[14];
    const float* hw2    = (const float*)d_in[15];
    const float* hb2    = (const float*)d_in[16];
    float* out = (float*)d_out;

    float *p_h, *p_hw, *p_tmp, *p_gsum, *p_gh;
    cudaGetSymbolAddress((void**)&p_h,    g_h);
    cudaGetSymbolAddress((void**)&p_hw,   g_hw);
    cudaGetSymbolAddress((void**)&p_tmp,  g_tmp);
    cudaGetSymbolAddress((void**)&p_gsum, g_gsum);
    cudaGetSymbolAddress((void**)&p_gh,   g_gh);

    const int TPB = 256;
    const int gN  = (NN + TPB - 1) / TPB;
    const int gE  = (EE + TPB - 1) / TPB;
    const int gWN = (NN + 7) / 8;
    const int gGm = (NN + 127) / 128;
    const int gGg = GG / 128;
    const int gGH = (GG*HH + TPB - 1) / TPB;

    const int SMB = 2 * 128 * 68 * 4;   // 69632 B dynamic smem
    cudaFuncSetAttribute(mma_gemm_k< 64,0,false>, cudaFuncAttributeMaxDynamicSharedMemorySize, SMB);
    cudaFuncSetAttribute(mma_gemm_k<128,0,false>, cudaFuncAttributeMaxDynamicSharedMemorySize, SMB);
    cudaFuncSetAttribute(mma_gemm_k<128,2,false>, cudaFuncAttributeMaxDynamicSharedMemorySize, SMB);
    cudaFuncSetAttribute(mma_gemm_k<128,3,true >, cudaFuncAttributeMaxDynamicSharedMemorySize, SMB);

    // CSR build (also produces dis = rsqrt(deg+1))
    csr_zero_k <<<gN, TPB>>>();
    csr_hist_k <<<gE, TPB>>>(dst);
    csr_scan1_k<<<NB, TPB>>>();
    csr_scan2_k<<<1,  TPB>>>();
    csr_scan3_k<<<gN, TPB>>>();
    csr_fill_k <<<gE, TPB>>>(src, dst);

    // input projection: h = x @ in_w.T + in_b
    mma_gemm_k<64,0,false><<<gGm, TPB, SMB>>>(x, nullptr, in_w, 64, in_b, p_h, NN, nullptr);

    // GCN layers: hw = h @ W.T ; h += LN(silu(gather(hw) + self + bias))
    for (int l = 0; l < 4; l++) {
        mma_gemm_k<128,0,false><<<gGm, TPB, SMB>>>(p_h, nullptr, conv_w + (size_t)l*HH*HH, 128,
                                                   nullptr, p_hw, NN, nullptr);
        gather_ln_k<<<gWN, TPB>>>(conv_b + l*HH, ln_g + l*HH, ln_b + l*HH);
    }

    // global mean pool -> per-graph head contribution gh = graph_emb @ W1b.T
    zero_pool_k<<<gGH, TPB>>>();
    pool_k     <<<gWN, TPB>>>(batch);
    pool_fin_k <<<gGH, TPB>>>();
    mma_gemm_k<128,0,false><<<gGg, TPB, SMB>>>(p_gsum, nullptr, hw1 + 128, 256, nullptr,
                                               p_gh, GG, nullptr);

    // physics MLP: t1 = silu(h@pw1.T+pb1) ; phys = t1@pw2.T+pb2
    mma_gemm_k<128,2,false><<<gGm, TPB, SMB>>>(p_h,  nullptr, pw1, 128, pb1, p_hw,  NN, nullptr);
    mma_gemm_k<128,0,false><<<gGm, TPB, SMB>>>(p_hw, nullptr, pw2, 128, pb2, p_tmp, NN, nullptr);

    // head: hid = silu((h+phys)@W1a.T + gh[batch] + b1) ; out = hid.w2 + b2
    mma_gemm_k<128,3,true><<<gGm, TPB, SMB>>>(p_h, p_tmp, hw1, 256, hb1, p_hw, NN, batch);
    dot_k<<<gWN, TPB>>>(hw2, hb2, out);
}

// round 6
// speedup vs baseline: 3.1215x; 1.0971x over previous
#include <cuda_runtime.h>
#include <cstdint>

#define NN 200000
#define EE 600000
#define GG 8192
#define HH 128
#define NB 196            // scan blocks: 196*1024 >= NN

// ---------------- scratch (device globals: allocation-free) ----------------
__device__ float g_h  [(size_t)NN*HH];
__device__ float g_hw [(size_t)NN*HH];
__device__ float g_tmp[(size_t)NN*HH];
__device__ float g_dis[NN];
__device__ float g_gsum[(size_t)GG*HH];
__device__ float g_cnt[GG];
__device__ float g_gh [(size_t)GG*HH];
__device__ float g_wc  [HH*HH];
__device__ float g_pw2t[HH*HH];
__device__ float g_c2  [HH];
// CSR
__device__ int g_deg[NN];
__device__ int g_fill[NN];
__device__ int g_rowptr[NN];
__device__ int g_csrc[EE];
__device__ int g_bsum[256];
__device__ int g_boff[256];

// ---------------- small helpers ----------------
__device__ __forceinline__ float4 ld4(const float* p){ return *reinterpret_cast<const float4*>(p); }
__device__ __forceinline__ void  st4(float* p, float4 v){ *reinterpret_cast<float4*>(p) = v; }
__device__ __forceinline__ void  st2(float* p, float a, float b){
    *reinterpret_cast<float2*>(p) = make_float2(a, b);
}
__device__ __forceinline__ float siluf(float x){ return x / (1.f + __expf(-x)); }
__device__ __forceinline__ float wredsum(float v){
#pragma unroll
    for (int o = 16; o; o >>= 1) v += __shfl_xor_sync(0xffffffffu, v, o);
    return v;
}
__device__ __forceinline__ uint32_t f2tf32(float f){
    uint32_t u;
    asm("cvt.rna.tf32.f32 %0, %1;" : "=r"(u) : "f"(f));
    return u;
}
__device__ __forceinline__ void mma1688(float* d, const uint32_t* a, const uint32_t* b){
    asm volatile("mma.sync.aligned.m16n8k8.row.col.f32.tf32.tf32.f32 "
        "{%0,%1,%2,%3}, {%4,%5,%6,%7}, {%8,%9}, {%0,%1,%2,%3};"
        : "+f"(d[0]), "+f"(d[1]), "+f"(d[2]), "+f"(d[3])
        : "r"(a[0]), "r"(a[1]), "r"(a[2]), "r"(a[3]), "r"(b[0]), "r"(b[1]));
}

// ---------------- CSR build ----------------
__global__ void csr_zero_k(){
    int i = blockIdx.x*blockDim.x + threadIdx.x;
    if (i < NN) { g_deg[i] = 0; g_fill[i] = 0; }
}
__global__ void csr_hist_k(const int* __restrict__ dst){
    int e = blockIdx.x*blockDim.x + threadIdx.x;
    if (e < EE) atomicAdd(&g_deg[dst[e]], 1);
}
__global__ __launch_bounds__(256) void csr_scan1_k(){
    __shared__ int ss[256];
    const int tid = threadIdx.x;
    const int i0  = blockIdx.x*1024 + tid*4;
    int v[4];
#pragma unroll
    for (int q = 0; q < 4; q++) v[q] = (i0+q < NN) ? g_deg[i0+q] : 0;
    int tsum = v[0]+v[1]+v[2]+v[3];
    ss[tid] = tsum; __syncthreads();
#pragma unroll
    for (int off = 1; off < 256; off <<= 1) {
        int t = (tid >= off) ? ss[tid-off] : 0;
        __syncthreads();
        ss[tid] += t;
        __syncthreads();
    }
    if (tid == 255) g_bsum[blockIdx.x] = ss[255];
    int run = ss[tid] - tsum;
#pragma unroll
    for (int q = 0; q < 4; q++) {
        if (i0+q < NN) { g_rowptr[i0+q] = run; run += v[q]; }
    }
}
__global__ __launch_bounds__(256) void csr_scan2_k(){
    __shared__ int ss[256];
    const int tid = threadIdx.x;
    int v = (tid < NB) ? g_bsum[tid] : 0;
    ss[tid] = v; __syncthreads();
#pragma unroll
    for (int off = 1; off < 256; off <<= 1) {
        int t = (tid >= off) ? ss[tid-off] : 0;
        __syncthreads();
        ss[tid] += t;
        __syncthreads();
    }
    if (tid < NB) g_boff[tid] = ss[tid] - v;   // exclusive
}
__global__ void csr_scan3_k(){
    int i = blockIdx.x*blockDim.x + threadIdx.x;
    if (i < NN) {
        g_rowptr[i] += g_boff[i >> 10];
        g_dis[i] = rsqrtf((float)g_deg[i] + 1.0f);
    }
}
__global__ void csr_fill_k(const int* __restrict__ src, const int* __restrict__ dst){
    int e = blockIdx.x*blockDim.x + threadIdx.x;
    if (e < EE) {
        int d = dst[e];
        int pos = g_rowptr[d] + atomicAdd(&g_fill[d], 1);
        g_csrc[pos] = src[e];
    }
}

// ---------------- weight prep --------------------------------------------
__global__ void transpose_pw2_k(const float* __restrict__ pw2){
    int i = blockIdx.x*blockDim.x + threadIdx.x;
    if (i < HH*HH) {
        int r = i >> 7, c = i & 127;
        g_pw2t[c*HH + r] = pw2[i];
    }
}
// c2[i] = sum_k W1a_h[i][k]*pb2[k] + hb1[i]
__global__ void c2_k(const float* __restrict__ hw1, const float* __restrict__ pb2,
                     const float* __restrict__ hb1){
    int i = threadIdx.x;
    float s = 0.f;
    for (int k = 0; k < HH; k++) s = fmaf(hw1[i*256 + k], pb2[k], s);
    g_c2[i] = s + hb1[i];
}
__global__ void out_init_k(float* __restrict__ out, const float* __restrict__ b2){
    int i = blockIdx.x*blockDim.x + threadIdx.x;
    if (i < NN) out[i] = b2[0];
}

// ---------------- TF32 tensor-core GEMM -------------------------------------
// out[M,128] = A[M,KT] @ W[128,KT]^T  (A row stride lda, W row stride ldw)
// EPI 0: out = acc (+bias if non-null) ; EPI 2: out = silu(acc + bias)
template<int KT, int EPI>
__global__ __launch_bounds__(256, 2) void mma_gemm_k(
    const float* __restrict__ A, int lda,
    const float* __restrict__ W, int ldw, const float* __restrict__ bias,
    float* __restrict__ out, int M)
{
    constexpr int KC  = 64;
    constexpr int LDSN = KC + 4;           // 68 floats
    extern __shared__ float smem[];
    float* As = smem;                       // [128][68]
    float* Ws = smem + 128*LDSN;            // [128][68]

    const int tid = threadIdx.x, wid = tid >> 5, lid = tid & 31;
    const int wm = wid & 3, wn = wid >> 2;
    const int g  = lid >> 2, t = lid & 3;
    const int brow = blockIdx.x * 128;

    float acc[2][8][4];
#pragma unroll
    for (int mt = 0; mt < 2; mt++)
#pragma unroll
        for (int nt = 0; nt < 8; nt++)
#pragma unroll
            for (int q = 0; q < 4; q++) acc[mt][nt][q] = 0.f;

    for (int k0 = 0; k0 < KT; k0 += KC) {
        if (k0) __syncthreads();
#pragma unroll
        for (int f = tid; f < 128*16; f += 256) {
            int row = f >> 4, kq = (f & 15) * 4;
            int gr = brow + row;
            float4 v = make_float4(0.f,0.f,0.f,0.f);
            if (gr < M) v = ld4(A + (size_t)gr*lda + k0 + kq);
            uint4 c = make_uint4(f2tf32(v.x), f2tf32(v.y), f2tf32(v.z), f2tf32(v.w));
            *reinterpret_cast<uint4*>(As + row*LDSN + kq) = c;
        }
#pragma unroll
        for (int f = tid; f < 128*16; f += 256) {
            int n = f >> 4, kq = (f & 15) * 4;
            float4 v = ld4(W + (size_t)n*ldw + k0 + kq);
            uint4 c = make_uint4(f2tf32(v.x), f2tf32(v.y), f2tf32(v.z), f2tf32(v.w));
            *reinterpret_cast<uint4*>(Ws + n*LDSN + kq) = c;
        }
        __syncthreads();

#pragma unroll
        for (int ks = 0; ks < KC/8; ks++) {
            const int kk = ks*8;
            uint32_t a[2][4], b[8][2];
#pragma unroll
            for (int mt = 0; mt < 2; mt++) {
                const float* ap = As + (wm*32 + mt*16 + g)*LDSN + kk + t;
                a[mt][0] = __float_as_uint(ap[0]);
                a[mt][1] = __float_as_uint(ap[8*LDSN]);
                a[mt][2] = __float_as_uint(ap[4]);
                a[mt][3] = __float_as_uint(ap[8*LDSN + 4]);
            }
#pragma unroll
            for (int nt = 0; nt < 8; nt++) {
                const float* bp = Ws + (wn*64 + nt*8 + g)*LDSN + kk + t;
                b[nt][0] = __float_as_uint(bp[0]);
                b[nt][1] = __float_as_uint(bp[4]);
            }
#pragma unroll
            for (int mt = 0; mt < 2; mt++)
#pragma unroll
                for (int nt = 0; nt < 8; nt++)
                    mma1688(acc[mt][nt], a[mt], b[nt]);
        }
    }

#pragma unroll
    for (int mt = 0; mt < 2; mt++) {
#pragma unroll
        for (int half = 0; half < 2; half++) {
            int row = brow + wm*32 + mt*16 + g + half*8;
            if (row >= M) continue;
            size_t ro = (size_t)row*HH;
#pragma unroll
            for (int nt = 0; nt < 8; nt++) {
                int col = wn*64 + nt*8 + t*2;
                float v0 = acc[mt][nt][half*2 + 0];
                float v1 = acc[mt][nt][half*2 + 1];
                if (EPI == 0) {
                    if (bias) { v0 += bias[col]; v1 += bias[col+1]; }
                } else if (EPI == 2) {
                    v0 = siluf(v0 + bias[col]); v1 = siluf(v1 + bias[col+1]);
                }
                st2(out + ro + col, v0, v1);
            }
        }
    }
}

// ---------------- head GEMM (K=256 split: [h ; t1], W split: [W1a_h ; Wc]) ---
// hid = silu(acc + c2 + gh[batch]) ; out[row] += hid . w2  (out pre-init to b2)
__global__ __launch_bounds__(256, 2) void head_gemm_k(
    const float* __restrict__ W1, const float* __restrict__ w2,
    const int* __restrict__ batch, float* __restrict__ out)
{
    constexpr int KC  = 64;
    constexpr int LDSN = KC + 4;
    extern __shared__ float smem[];
    float* As = smem;
    float* Ws = smem + 128*LDSN;

    const int tid = threadIdx.x, wid = tid >> 5, lid = tid & 31;
    const int wm = wid & 3, wn = wid >> 2;
    const int g  = lid >> 2, t = lid & 3;
    const int brow = blockIdx.x * 128;

    float acc[2][8][4];
#pragma unroll
    for (int mt = 0; mt < 2; mt++)
#pragma unroll
        for (int nt = 0; nt < 8; nt++)
#pragma unroll
            for (int q = 0; q < 4; q++) acc[mt][nt][q] = 0.f;

    for (int k0 = 0; k0 < 256; k0 += KC) {
        if (k0) __syncthreads();
        const float* Ap = (k0 < 128) ? g_h : g_tmp;
        const int ka = k0 & 127;
#pragma unroll
        for (int f = tid; f < 128*16; f += 256) {
            int row = f >> 4, kq = (f & 15) * 4;
            int gr = brow + row;
            float4 v = make_float4(0.f,0.f,0.f,0.f);
            if (gr < NN) v = ld4(Ap + (size_t)gr*HH + ka + kq);
            uint4 c = make_uint4(f2tf32(v.x), f2tf32(v.y), f2tf32(v.z), f2tf32(v.w));
            *reinterpret_cast<uint4*>(As + row*LDSN + kq) = c;
        }
#pragma unroll
        for (int f = tid; f < 128*16; f += 256) {
            int n = f >> 4, kq = (f & 15) * 4;
            float4 v;
            if (k0 < 128) v = ld4(W1 + (size_t)n*256 + k0 + kq);
            else          v = ld4(g_wc + (size_t)n*HH + ka + kq);
            uint4 c = make_uint4(f2tf32(v.x), f2tf32(v.y), f2tf32(v.z), f2tf32(v.w));
            *reinterpret_cast<uint4*>(Ws + n*LDSN + kq) = c;
        }
        __syncthreads();

#pragma unroll
        for (int ks = 0; ks < KC/8; ks++) {
            const int kk = ks*8;
            uint32_t a[2][4], b[8][2];
#pragma unroll
            for (int mt = 0; mt < 2; mt++) {
                const float* ap = As + (wm*32 + mt*16 + g)*LDSN + kk + t;
                a[mt][0] = __float_as_uint(ap[0]);
                a[mt][1] = __float_as_uint(ap[8*LDSN]);
                a[mt][2] = __float_as_uint(ap[4]);
                a[mt][3] = __float_as_uint(ap[8*LDSN + 4]);
            }
#pragma unroll
            for (int nt = 0; nt < 8; nt++) {
                const float* bp = Ws + (wn*64 + nt*8 + g)*LDSN + kk + t;
                b[nt][0] = __float_as_uint(bp[0]);
                b[nt][1] = __float_as_uint(bp[4]);
            }
#pragma unroll
            for (int mt = 0; mt < 2; mt++)
#pragma unroll
                for (int nt = 0; nt < 8; nt++)
                    mma1688(acc[mt][nt], a[mt], b[nt]);
        }
    }

#pragma unroll
    for (int mt = 0; mt < 2; mt++) {
#pragma unroll
        for (int half = 0; half < 2; half++) {
            int row = brow + wm*32 + mt*16 + g + half*8;
            float partial = 0.f;
            if (row < NN) {
                const float* ghrow = g_gh + (size_t)batch[row]*HH;
#pragma unroll
                for (int nt = 0; nt < 8; nt++) {
                    int col = wn*64 + nt*8 + t*2;
                    float v0 = siluf(acc[mt][nt][half*2+0] + g_c2[col]   + ghrow[col]);
                    float v1 = siluf(acc[mt][nt][half*2+1] + g_c2[col+1] + ghrow[col+1]);
                    partial = fmaf(v0, w2[col], partial);
                    partial = fmaf(v1, w2[col+1], partial);
                }
            }
            partial += __shfl_xor_sync(0xffffffffu, partial, 1);
            partial += __shfl_xor_sync(0xffffffffu, partial, 2);
            if (t == 0 && row < NN)
                asm volatile("red.global.add.f32 [%0], %1;" :: "l"(out + row), "f"(partial) : "memory");
        }
    }
}

// ---- fused neighbor-gather + self-loop + bias + silu + LN + residual (+pool)
template<bool POOL>
__global__ __launch_bounds__(256) void gather_ln_k(const float* __restrict__ bias,
                                                   const float* __restrict__ lng,
                                                   const float* __restrict__ lnb,
                                                   const int* __restrict__ batch)
{
    int row = blockIdx.x * 8 + (threadIdx.x >> 5);
    if (row >= NN) return;
    int lane = threadIdx.x & 31;
    const int cnt   = g_deg[row];
    const int start = g_rowptr[row];
    const float di  = g_dis[row];
    size_t off = (size_t)row*HH + lane*4;

    float4 a  = ld4(g_hw + off);
    float4 b4 = ld4(bias + lane*4);
    float sn  = di * di;
    float ax = fmaf(a.x, sn, b4.x), ay = fmaf(a.y, sn, b4.y);
    float az = fmaf(a.z, sn, b4.z), aw = fmaf(a.w, sn, b4.w);

    for (int j = 0; j < cnt; j++) {
        int s   = g_csrc[start + j];
        float w = g_dis[s] * di;
        float4 v = ld4(g_hw + (size_t)s*HH + lane*4);
        ax = fmaf(v.x, w, ax); ay = fmaf(v.y, w, ay);
        az = fmaf(v.z, w, az); aw = fmaf(v.w, w, aw);
    }

    float s0 = siluf(ax), s1 = siluf(ay), s2 = siluf(az), s3 = siluf(aw);
    float sum = wredsum(s0+s1+s2+s3);
    float sq  = wredsum(s0*s0 + s1*s1 + s2*s2 + s3*s3);
    float mu  = sum * (1.f/128.f);
    float var = sq * (1.f/128.f) - mu*mu;
    float inv = rsqrtf(var + 1e-5f);
    float4 h = ld4(g_h + off);
    int c = lane*4;
    h.x += (s0 - mu)*inv*lng[c+0] + lnb[c+0];
    h.y += (s1 - mu)*inv*lng[c+1] + lnb[c+1];
    h.z += (s2 - mu)*inv*lng[c+2] + lnb[c+2];
    h.w += (s3 - mu)*inv*lng[c+3] + lnb[c+3];
    st4(g_h + off, h);

    if (POOL) {
        int b = batch[row];
        float* p = g_gsum + (size_t)b*HH + lane*4;
        asm volatile("red.global.add.v4.f32 [%0], {%1,%2,%3,%4};"
                     :: "l"(p), "f"(h.x), "f"(h.y), "f"(h.z), "f"(h.w) : "memory");
        if (lane == 0) atomicAdd(&g_cnt[b], 1.0f);
    }
}

// ---------------- global mean pool finalize ----------------
__global__ void zero_pool_k(){
    int i = blockIdx.x*blockDim.x + threadIdx.x;
    if (i < GG*HH) g_gsum[i] = 0.f;
    if (i < GG)    g_cnt[i]  = 0.f;
}
__global__ void pool_fin_k(){
    int i = blockIdx.x*blockDim.x + threadIdx.x;
    if (i < GG*HH) {
        int g = i / HH;
        g_gsum[i] = g_gsum[i] / fmaxf(g_cnt[g], 1.0f);
    }
}

// ---------------- launch ----------------
extern "C" void kernel_launch(void* const* d_in, const int* in_sizes, int n_in,
                              void* d_out, int out_size)
{
    const float* x      = (const float*)d_in[0];
    const int*   ei     = (const int*)  d_in[1];
    const int*   src    = ei;
    const int*   dst    = ei + EE;
    const int*   batch  = (const int*)  d_in[2];
    const float* in_w   = (const float*)d_in[3];
    const float* in_b   = (const float*)d_in[4];
    const float* conv_w = (const float*)d_in[5];
    const float* conv_b = (const float*)d_in[6];
    const float* ln_g   = (const float*)d_in[7];
    const float* ln_b   = (const float*)d_in[8];
    const float* pw1    = (const float*)d_in[9];
    const float* pb1    = (const float*)d_in[10];
    const float* pw2    = (const float*)d_in[11];
    const float* pb2    = (const float*)d_in[12];
    const float* hw1    = (const float*)d_in[13];
    const float* hb1    = (const float*)d_in[14];
    const float* hw2    = (const float*)d_in[15];
    const float* hb2    = (const float*)d_in[16];
    float* out = (float*)d_out;

    float *p_h, *p_hw, *p_tmp, *p_gsum, *p_gh, *p_wc, *p_pw2t;
    cudaGetSymbolAddress((void**)&p_h,    g_h);
    cudaGetSymbolAddress((void**)&p_hw,   g_hw);
    cudaGetSymbolAddress((void**)&p_tmp,  g_tmp);
    cudaGetSymbolAddress((void**)&p_gsum, g_gsum);
    cudaGetSymbolAddress((void**)&p_gh,   g_gh);
    cudaGetSymbolAddress((void**)&p_wc,   g_wc);
    cudaGetSymbolAddress((void**)&p_pw2t, g_pw2t);

    const int TPB = 256;
    const int gN  = (NN + TPB - 1) / TPB;
    const int gE  = (EE + TPB - 1) / TPB;
    const int gWN = (NN + 7) / 8;
    const int gGm = (NN + 127) / 128;
    const int gGg = GG / 128;
    const int gGH = (GG*HH + TPB - 1) / TPB;
    const int gHW = (HH*HH + TPB - 1) / TPB;

    const int SMB = 2 * 128 * 68 * 4;   // 69632 B dynamic smem
    cudaFuncSetAttribute(mma_gemm_k< 64,0>, cudaFuncAttributeMaxDynamicSharedMemorySize, SMB);
    cudaFuncSetAttribute(mma_gemm_k<128,0>, cudaFuncAttributeMaxDynamicSharedMemorySize, SMB);
    cudaFuncSetAttribute(mma_gemm_k<128,2>, cudaFuncAttributeMaxDynamicSharedMemorySize, SMB);
    cudaFuncSetAttribute(head_gemm_k,       cudaFuncAttributeMaxDynamicSharedMemorySize, SMB);

    // CSR build + pool zero + weight prep
    zero_pool_k<<<gGH, TPB>>>();
    csr_zero_k <<<gN, TPB>>>();
    csr_hist_k <<<gE, TPB>>>(dst);
    csr_scan1_k<<<NB, TPB>>>();
    csr_scan2_k<<<1,  TPB>>>();
    csr_scan3_k<<<gN, TPB>>>();
    csr_fill_k <<<gE, TPB>>>(src, dst);

    transpose_pw2_k<<<gHW, TPB>>>(pw2);
    // Wc = W1a_h @ pw2  (A = hw1 rows 0..127 cols 0..127, lda 256; W = pw2t, ldw 128)
    mma_gemm_k<128,0><<<1, TPB, SMB>>>(hw1, 256, p_pw2t, 128, nullptr, p_wc, 128);
    c2_k<<<1, 128>>>(hw1, pb2, hb1);
    out_init_k<<<gN, TPB>>>(out, hb2);

    // input projection: h = x @ in_w.T + in_b
    mma_gemm_k<64,0><<<gGm, TPB, SMB>>>(x, 64, in_w, 64, in_b, p_h, NN);

    // GCN layers: hw = h @ W.T ; h += LN(silu(gather(hw) + self + bias))
    for (int l = 0; l < 4; l++) {
        mma_gemm_k<128,0><<<gGm, TPB, SMB>>>(p_h, 128, conv_w + (size_t)l*HH*HH, 128,
                                             nullptr, p_hw, NN);
        if (l < 3) gather_ln_k<false><<<gWN, TPB>>>(conv_b + l*HH, ln_g + l*HH, ln_b + l*HH, batch);
        else       gather_ln_k<true ><<<gWN, TPB>>>(conv_b + l*HH, ln_g + l*HH, ln_b + l*HH, batch);
    }

    // pool finalize -> gh = graph_emb @ W1b.T
    pool_fin_k<<<gGH, TPB>>>();
    mma_gemm_k<128,0><<<gGg, TPB, SMB>>>(p_gsum, 128, hw1 + 128, 256, nullptr, p_gh, GG);

    // physics MLP part 1: t1 = silu(h@pw1.T+pb1)
    mma_gemm_k<128,2><<<gGm, TPB, SMB>>>(p_h, 128, pw1, 128, pb1, p_tmp, NN);

    // head (phys2 folded in): out[row] = b2 + silu([h;t1]@[W1a_h;Wc].T + c2 + gh[batch]) . w2
    head_gemm_k<<<gGm, TPB, SMB>>>(hw1, hw2, batch, out);
}

// round 9
// speedup vs baseline: 3.2203x; 1.0316x over previous
#include <cuda_runtime.h>
#include <cuda_fp16.h>
#include <cstdint>

#define NN 200000
#define EE 600000
#define GG 8192
#define HH 128
#define NB 196            // scan blocks: 196*1024 >= NN

// ---------------- scratch (device globals: allocation-free) ----------------
__device__ float  g_h  [(size_t)NN*HH];
__device__ __half g_hw [(size_t)NN*HH];     // conv outputs (fp16)
__device__ __half g_t1 [(size_t)NN*HH];     // phys1 output (fp16)
__device__ float  g_dis[NN];
__device__ float  g_gsum[(size_t)GG*HH];
__device__ float  g_cnt[GG];
__device__ float  g_gh [(size_t)GG*HH];
__device__ float  g_wc  [HH*HH];
__device__ float  g_pw2t[HH*HH];
__device__ float  g_c2  [HH];
// CSR
__device__ int g_deg[NN];
__device__ int g_fill[NN];
__device__ int g_rowptr[NN];
__device__ int g_csrc[EE];
__device__ int g_bsum[256];
__device__ int g_boff[256];

// ---------------- small helpers ----------------
__device__ __forceinline__ float4 ld4(const float* p){ return *reinterpret_cast<const float4*>(p); }
__device__ __forceinline__ void  st4(float* p, float4 v){ *reinterpret_cast<float4*>(p) = v; }
__device__ __forceinline__ void ldh4(const __half* p, float& x, float& y, float& z, float& w){
    uint2 u = *reinterpret_cast<const uint2*>(p);
    float2 f0 = __half22float2(*reinterpret_cast<__half2*>(&u.x));
    float2 f1 = __half22float2(*reinterpret_cast<__half2*>(&u.y));
    x = f0.x; y = f0.y; z = f1.x; w = f1.y;
}
__device__ __forceinline__ float siluf(float x){ return x / (1.f + __expf(-x)); }
__device__ __forceinline__ float wredsum(float v){
#pragma unroll
    for (int o = 16; o; o >>= 1) v += __shfl_xor_sync(0xffffffffu, v, o);
    return v;
}
__device__ __forceinline__ uint32_t f2tf32(float f){
    uint32_t u;
    asm("cvt.rna.tf32.f32 %0, %1;" : "=r"(u) : "f"(f));
    return u;
}
__device__ __forceinline__ void mma1688(float* d, const uint32_t* a, const uint32_t* b){
    asm volatile("mma.sync.aligned.m16n8k8.row.col.f32.tf32.tf32.f32 "
        "{%0,%1,%2,%3}, {%4,%5,%6,%7}, {%8,%9}, {%0,%1,%2,%3};"
        : "+f"(d[0]), "+f"(d[1]), "+f"(d[2]), "+f"(d[3])
        : "r"(a[0]), "r"(a[1]), "r"(a[2]), "r"(a[3]), "r"(b[0]), "r"(b[1]));
}

// ---------------- CSR build ----------------
__global__ void csr_zero_k(){
    int i = blockIdx.x*blockDim.x + threadIdx.x;
    if (i < NN) { g_deg[i] = 0; g_fill[i] = 0; }
}
__global__ void csr_hist_k(const int* __restrict__ dst){
    int e = blockIdx.x*blockDim.x + threadIdx.x;
    if (e < EE) atomicAdd(&g_deg[dst[e]], 1);
}
__global__ __launch_bounds__(256) void csr_scan1_k(){
    __shared__ int ss[256];
    const int tid = threadIdx.x;
    const int i0  = blockIdx.x*1024 + tid*4;
    int v[4];
#pragma unroll
    for (int q = 0; q < 4; q++) v[q] = (i0+q < NN) ? g_deg[i0+q] : 0;
    int tsum = v[0]+v[1]+v[2]+v[3];
    ss[tid] = tsum; __syncthreads();
#pragma unroll
    for (int off = 1; off < 256; off <<= 1) {
        int t = (tid >= off) ? ss[tid-off] : 0;
        __syncthreads();
        ss[tid] += t;
        __syncthreads();
    }
    if (tid == 255) g_bsum[blockIdx.x] = ss[255];
    int run = ss[tid] - tsum;
#pragma unroll
    for (int q = 0; q < 4; q++) {
        if (i0+q < NN) { g_rowptr[i0+q] = run; run += v[q]; }
    }
}
__global__ __launch_bounds__(256) void csr_scan2_k(){
    __shared__ int ss[256];
    const int tid = threadIdx.x;
    int v = (tid < NB) ? g_bsum[tid] : 0;
    ss[tid] = v; __syncthreads();
#pragma unroll
    for (int off = 1; off < 256; off <<= 1) {
        int t = (tid >= off) ? ss[tid-off] : 0;
        __syncthreads();
        ss[tid] += t;
        __syncthreads();
    }
    if (tid < NB) g_boff[tid] = ss[tid] - v;   // exclusive
}
__global__ void csr_scan3_k(){
    int i = blockIdx.x*blockDim.x + threadIdx.x;
    if (i < NN) {
        g_rowptr[i] += g_boff[i >> 10];
        g_dis[i] = rsqrtf((float)g_deg[i] + 1.0f);
    }
}
__global__ void csr_fill_k(const int* __restrict__ src, const int* __restrict__ dst){
    int e = blockIdx.x*blockDim.x + threadIdx.x;
    if (e < EE) {
        int d = dst[e];
        int pos = g_rowptr[d] + atomicAdd(&g_fill[d], 1);
        g_csrc[pos] = src[e];
    }
}

// ---------------- weight prep --------------------------------------------
__global__ void transpose_pw2_k(const float* __restrict__ pw2){
    int i = blockIdx.x*blockDim.x + threadIdx.x;
    if (i < HH*HH) {
        int r = i >> 7, c = i & 127;
        g_pw2t[c*HH + r] = pw2[i];
    }
}
__global__ void c2_k(const float* __restrict__ hw1, const float* __restrict__ pb2,
                     const float* __restrict__ hb1){
    int i = threadIdx.x;
    float s = 0.f;
    for (int k = 0; k < HH; k++) s = fmaf(hw1[i*256 + k], pb2[k], s);
    g_c2[i] = s + hb1[i];
}
__global__ void out_init_k(float* __restrict__ out, const float* __restrict__ b2){
    int i = blockIdx.x*blockDim.x + threadIdx.x;
    if (i < NN) out[i] = b2[0];
}

// ---------------- TF32 tensor-core GEMM -------------------------------------
// out[M,128] = A[M,KT] @ W[128,KT]^T  (A row stride lda, W row stride ldw)
// EPI 0: out = acc (+bias if non-null) ; EPI 2: out = silu(acc + bias)
// OUTH: write fp16 (half2) instead of fp32
template<int KT, int EPI, bool OUTH>
__global__ __launch_bounds__(256, 2) void mma_gemm_k(
    const float* __restrict__ A, int lda,
    const float* __restrict__ W, int ldw, const float* __restrict__ bias,
    void* __restrict__ outv, int M)
{
    constexpr int KC  = 64;
    constexpr int LDSN = KC + 4;           // 68 floats
    extern __shared__ float smem[];
    float* As = smem;                       // [128][68]
    float* Ws = smem + 128*LDSN;            // [128][68]

    const int tid = threadIdx.x, wid = tid >> 5, lid = tid & 31;
    const int wm = wid & 3, wn = wid >> 2;
    const int g  = lid >> 2, t = lid & 3;
    const int brow = blockIdx.x * 128;

    float acc[2][8][4];
#pragma unroll
    for (int mt = 0; mt < 2; mt++)
#pragma unroll
        for (int nt = 0; nt < 8; nt++)
#pragma unroll
            for (int q = 0; q < 4; q++) acc[mt][nt][q] = 0.f;

    for (int k0 = 0; k0 < KT; k0 += KC) {
        if (k0) __syncthreads();
#pragma unroll
        for (int f = tid; f < 128*16; f += 256) {
            int row = f >> 4, kq = (f & 15) * 4;
            int gr = brow + row;
            float4 v = make_float4(0.f,0.f,0.f,0.f);
            if (gr < M) v = ld4(A + (size_t)gr*lda + k0 + kq);
            uint4 c = make_uint4(f2tf32(v.x), f2tf32(v.y), f2tf32(v.z), f2tf32(v.w));
            *reinterpret_cast<uint4*>(As + row*LDSN + kq) = c;
        }
#pragma unroll
        for (int f = tid; f < 128*16; f += 256) {
            int n = f >> 4, kq = (f & 15) * 4;
            float4 v = ld4(W + (size_t)n*ldw + k0 + kq);
            uint4 c = make_uint4(f2tf32(v.x), f2tf32(v.y), f2tf32(v.z), f2tf32(v.w));
            *reinterpret_cast<uint4*>(Ws + n*LDSN + kq) = c;
        }
        __syncthreads();

#pragma unroll
        for (int ks = 0; ks < KC/8; ks++) {
            const int kk = ks*8;
            uint32_t a[2][4], b[8][2];
#pragma unroll
            for (int mt = 0; mt < 2; mt++) {
                const float* ap = As + (wm*32 + mt*16 + g)*LDSN + kk + t;
                a[mt][0] = __float_as_uint(ap[0]);
                a[mt][1] = __float_as_uint(ap[8*LDSN]);
                a[mt][2] = __float_as_uint(ap[4]);
                a[mt][3] = __float_as_uint(ap[8*LDSN + 4]);
            }
#pragma unroll
            for (int nt = 0; nt < 8; nt++) {
                const float* bp = Ws + (wn*64 + nt*8 + g)*LDSN + kk + t;
                b[nt][0] = __float_as_uint(bp[0]);
                b[nt][1] = __float_as_uint(bp[4]);
            }
#pragma unroll
            for (int mt = 0; mt < 2; mt++)
#pragma unroll
                for (int nt = 0; nt < 8; nt++)
                    mma1688(acc[mt][nt], a[mt], b[nt]);
        }
    }

    float*  outf = (float*) outv;
    __half* outh = (__half*)outv;
#pragma unroll
    for (int mt = 0; mt < 2; mt++) {
#pragma unroll
        for (int half = 0; half < 2; half++) {
            int row = brow + wm*32 + mt*16 + g + half*8;
            if (row >= M) continue;
            size_t ro = (size_t)row*HH;
#pragma unroll
            for (int nt = 0; nt < 8; nt++) {
                int col = wn*64 + nt*8 + t*2;
                float v0 = acc[mt][nt][half*2 + 0];
                float v1 = acc[mt][nt][half*2 + 1];
                if (EPI == 0) {
                    if (bias) { v0 += bias[col]; v1 += bias[col+1]; }
                } else if (EPI == 2) {
                    v0 = siluf(v0 + bias[col]); v1 = siluf(v1 + bias[col+1]);
                }
                if (OUTH) {
                    *reinterpret_cast<__half2*>(outh + ro + col) = __floats2half2_rn(v0, v1);
                } else {
                    *reinterpret_cast<float2*>(outf + ro + col) = make_float2(v0, v1);
                }
            }
        }
    }
}

// ---------------- head GEMM (K=256 split: [h ; t1], W split: [W1a_h ; Wc]) ---
// hid = silu(acc + c2 + gh[batch]) ; out[row] += hid . w2  (out pre-init to b2)
__global__ __launch_bounds__(256, 2) void head_gemm_k(
    const float* __restrict__ W1, const float* __restrict__ w2,
    const int* __restrict__ batch, float* __restrict__ out)
{
    constexpr int KC  = 64;
    constexpr int LDSN = KC + 4;
    extern __shared__ float smem[];
    float* As = smem;
    float* Ws = smem + 128*LDSN;

    const int tid = threadIdx.x, wid = tid >> 5, lid = tid & 31;
    const int wm = wid & 3, wn = wid >> 2;
    const int g  = lid >> 2, t = lid & 3;
    const int brow = blockIdx.x * 128;

    float acc[2][8][4];
#pragma unroll
    for (int mt = 0; mt < 2; mt++)
#pragma unroll
        for (int nt = 0; nt < 8; nt++)
#pragma unroll
            for (int q = 0; q < 4; q++) acc[mt][nt][q] = 0.f;

    for (int k0 = 0; k0 < 256; k0 += KC) {
        if (k0) __syncthreads();
        const int ka = k0 & 127;
#pragma unroll
        for (int f = tid; f < 128*16; f += 256) {
            int row = f >> 4, kq = (f & 15) * 4;
            int gr = brow + row;
            float4 v = make_float4(0.f,0.f,0.f,0.f);
            if (gr < NN) {
                if (k0 < 128) v = ld4(g_h + (size_t)gr*HH + ka + kq);
                else          ldh4(g_t1 + (size_t)gr*HH + ka + kq, v.x, v.y, v.z, v.w);
            }
            uint4 c = make_uint4(f2tf32(v.x), f2tf32(v.y), f2tf32(v.z), f2tf32(v.w));
            *reinterpret_cast<uint4*>(As + row*LDSN + kq) = c;
        }
#pragma unroll
        for (int f = tid; f < 128*16; f += 256) {
            int n = f >> 4, kq = (f & 15) * 4;
            float4 v;
            if (k0 < 128) v = ld4(W1 + (size_t)n*256 + k0 + kq);
            else          v = ld4(g_wc + (size_t)n*HH + ka + kq);
            uint4 c = make_uint4(f2tf32(v.x), f2tf32(v.y), f2tf32(v.z), f2tf32(v.w));
            *reinterpret_cast<uint4*>(Ws + n*LDSN + kq) = c;
        }
        __syncthreads();

#pragma unroll
        for (int ks = 0; ks < KC/8; ks++) {
            const int kk = ks*8;
            uint32_t a[2][4], b[8][2];
#pragma unroll
            for (int mt = 0; mt < 2; mt++) {
                const float* ap = As + (wm*32 + mt*16 + g)*LDSN + kk + t;
                a[mt][0] = __float_as_uint(ap[0]);
                a[mt][1] = __float_as_uint(ap[8*LDSN]);
                a[mt][2] = __float_as_uint(ap[4]);
                a[mt][3] = __float_as_uint(ap[8*LDSN + 4]);
            }
#pragma unroll
            for (int nt = 0; nt < 8; nt++) {
                const float* bp = Ws + (wn*64 + nt*8 + g)*LDSN + kk + t;
                b[nt][0] = __float_as_uint(bp[0]);
                b[nt][1] = __float_as_uint(bp[4]);
            }
#pragma unroll
            for (int mt = 0; mt < 2; mt++)
#pragma unroll
                for (int nt = 0; nt < 8; nt++)
                    mma1688(acc[mt][nt], a[mt], b[nt]);
        }
    }

#pragma unroll
    for (int mt = 0; mt < 2; mt++) {
#pragma unroll
        for (int half = 0; half < 2; half++) {
            int row = brow + wm*32 + mt*16 + g + half*8;
            float partial = 0.f;
            if (row < NN) {
                const float* ghrow = g_gh + (size_t)batch[row]*HH;
#pragma unroll
                for (int nt = 0; nt < 8; nt++) {
                    int col = wn*64 + nt*8 + t*2;
                    float v0 = siluf(acc[mt][nt][half*2+0] + g_c2[col]   + ghrow[col]);
                    float v1 = siluf(acc[mt][nt][half*2+1] + g_c2[col+1] + ghrow[col+1]);
                    partial = fmaf(v0, w2[col], partial);
                    partial = fmaf(v1, w2[col+1], partial);
                }
            }
            partial += __shfl_xor_sync(0xffffffffu, partial, 1);
            partial += __shfl_xor_sync(0xffffffffu, partial, 2);
            if (t == 0 && row < NN)
                asm volatile("red.global.add.f32 [%0], %1;" :: "l"(out + row), "f"(partial) : "memory");
        }
    }
}

// ---- fused neighbor-gather + self-loop + bias + silu + LN + residual (+pool)
template<bool POOL>
__global__ __launch_bounds__(256) void gather_ln_k(const float* __restrict__ bias,
                                                   const float* __restrict__ lng,
                                                   const float* __restrict__ lnb,
                                                   const int* __restrict__ batch)
{
    int row = blockIdx.x * 8 + (threadIdx.x >> 5);
    if (row >= NN) return;
    int lane = threadIdx.x & 31;
    const int cnt   = g_deg[row];
    const int start = g_rowptr[row];
    const float di  = g_dis[row];
    size_t off = (size_t)row*HH + lane*4;

    float ax, ay, az, aw;
    ldh4(g_hw + off, ax, ay, az, aw);
    float4 b4 = ld4(bias + lane*4);
    float sn  = di * di;
    ax = fmaf(ax, sn, b4.x); ay = fmaf(ay, sn, b4.y);
    az = fmaf(az, sn, b4.z); aw = fmaf(aw, sn, b4.w);

    for (int j = 0; j < cnt; j++) {
        int s   = g_csrc[start + j];
        float w = g_dis[s] * di;
        float vx, vy, vz, vw;
        ldh4(g_hw + (size_t)s*HH + lane*4, vx, vy, vz, vw);
        ax = fmaf(vx, w, ax); ay = fmaf(vy, w, ay);
        az = fmaf(vz, w, az); aw = fmaf(vw, w, aw);
    }

    float s0 = siluf(ax), s1 = siluf(ay), s2 = siluf(az), s3 = siluf(aw);
    float sum = wredsum(s0+s1+s2+s3);
    float sq  = wredsum(s0*s0 + s1*s1 + s2*s2 + s3*s3);
    float mu  = sum * (1.f/128.f);
    float var = sq * (1.f/128.f) - mu*mu;
    float inv = rsqrtf(var + 1e-5f);
    float4 h = ld4(g_h + off);
    int c = lane*4;
    h.x += (s0 - mu)*inv*lng[c+0] + lnb[c+0];
    h.y += (s1 - mu)*inv*lng[c+1] + lnb[c+1];
    h.z += (s2 - mu)*inv*lng[c+2] + lnb[c+2];
    h.w += (s3 - mu)*inv*lng[c+3] + lnb[c+3];
    st4(g_h + off, h);

    if (POOL) {
        int b = batch[row];
        float* p = g_gsum + (size_t)b*HH + lane*4;
        asm volatile("red.global.add.v4.f32 [%0], {%1,%2,%3,%4};"
                     :: "l"(p), "f"(h.x), "f"(h.y), "f"(h.z), "f"(h.w) : "memory");
        if (lane == 0) atomicAdd(&g_cnt[b], 1.0f);
    }
}

// ---------------- global mean pool finalize ----------------
__global__ void zero_pool_k(){
    int i = blockIdx.x*blockDim.x + threadIdx.x;
    if (i < GG*HH) g_gsum[i] = 0.f;
    if (i < GG)    g_cnt[i]  = 0.f;
}
__global__ void pool_fin_k(){
    int i = blockIdx.x*blockDim.x + threadIdx.x;
    if (i < GG*HH) {
        int g = i / HH;
        g_gsum[i] = g_gsum[i] / fmaxf(g_cnt[g], 1.0f);
    }
}

// ---------------- launch ----------------
extern "C" void kernel_launch(void* const* d_in, const int* in_sizes, int n_in,
                              void* d_out, int out_size)
{
    const float* x      = (const float*)d_in[0];
    const int*   ei     = (const int*)  d_in[1];
    const int*   src    = ei;
    const int*   dst    = ei + EE;
    const int*   batch  = (const int*)  d_in[2];
    const float* in_w   = (const float*)d_in[3];
    const float* in_b   = (const float*)d_in[4];
    const float* conv_w = (const float*)d_in[5];
    const float* conv_b = (const float*)d_in[6];
    const float* ln_g   = (const float*)d_in[7];
    const float* ln_b   = (const float*)d_in[8];
    const float* pw1    = (const float*)d_in[9];
    const float* pb1    = (const float*)d_in[10];
    const float* pw2    = (const float*)d_in[11];
    const float* pb2    = (const float*)d_in[12];
    const float* hw1    = (const float*)d_in[13];
    const float* hb1    = (const float*)d_in[14];
    const float* hw2    = (const float*)d_in[15];
    const float* hb2    = (const float*)d_in[16];
    float* out = (float*)d_out;

    float *p_h, *p_gsum, *p_gh, *p_wc, *p_pw2t;
    __half *p_hw, *p_t1;
    cudaGetSymbolAddress((void**)&p_h,    g_h);
    cudaGetSymbolAddress((void**)&p_hw,   g_hw);
    cudaGetSymbolAddress((void**)&p_t1,   g_t1);
    cudaGetSymbolAddress((void**)&p_gsum, g_gsum);
    cudaGetSymbolAddress((void**)&p_gh,   g_gh);
    cudaGetSymbolAddress((void**)&p_wc,   g_wc);
    cudaGetSymbolAddress((void**)&p_pw2t, g_pw2t);

    const int TPB = 256;
    const int gN  = (NN + TPB - 1) / TPB;
    const int gE  = (EE + TPB - 1) / TPB;
    const int gWN = (NN + 7) / 8;
    const int gGm = (NN + 127) / 128;
    const int gGg = GG / 128;
    const int gGH = (GG*HH + TPB - 1) / TPB;
    const int gHW = (HH*HH + TPB - 1) / TPB;

    const int SMB = 2 * 128 * 68 * 4;   // 69632 B dynamic smem
    cudaFuncSetAttribute(mma_gemm_k< 64,0,false>, cudaFuncAttributeMaxDynamicSharedMemorySize, SMB);
    cudaFuncSetAttribute(mma_gemm_k<128,0,false>, cudaFuncAttributeMaxDynamicSharedMemorySize, SMB);
    cudaFuncSetAttribute(mma_gemm_k<128,0,true >, cudaFuncAttributeMaxDynamicSharedMemorySize, SMB);
    cudaFuncSetAttribute(mma_gemm_k<128,2,true >, cudaFuncAttributeMaxDynamicSharedMemorySize, SMB);
    cudaFuncSetAttribute(head_gemm_k,             cudaFuncAttributeMaxDynamicSharedMemorySize, SMB);

    // CSR build + pool zero + weight prep
    zero_pool_k<<<gGH, TPB>>>();
    csr_zero_k <<<gN, TPB>>>();
    csr_hist_k <<<gE, TPB>>>(dst);
    csr_scan1_k<<<NB, TPB>>>();
    csr_scan2_k<<<1,  TPB>>>();
    csr_scan3_k<<<gN, TPB>>>();
    csr_fill_k <<<gE, TPB>>>(src, dst);

    transpose_pw2_k<<<gHW, TPB>>>(pw2);
    // Wc = W1a_h @ pw2
    mma_gemm_k<128,0,false><<<1, TPB, SMB>>>(hw1, 256, p_pw2t, 128, nullptr, p_wc, 128);
    c2_k<<<1, 128>>>(hw1, pb2, hb1);
    out_init_k<<<gN, TPB>>>(out, hb2);

    // input projection: h = x @ in_w.T + in_b
    mma_gemm_k<64,0,false><<<gGm, TPB, SMB>>>(x, 64, in_w, 64, in_b, p_h, NN);

    // GCN layers: hw = h @ W.T (fp16) ; h += LN(silu(gather(hw) + self + bias))
    for (int l = 0; l < 4; l++) {
        mma_gemm_k<128,0,true><<<gGm, TPB, SMB>>>(p_h, 128, conv_w + (size_t)l*HH*HH, 128,
                                                  nullptr, p_hw, NN);
        if (l < 3) gather_ln_k<false><<<gWN, TPB>>>(conv_b + l*HH, ln_g + l*HH, ln_b + l*HH, batch);
        else       gather_ln_k<true ><<<gWN, TPB>>>(conv_b + l*HH, ln_g + l*HH, ln_b + l*HH, batch);
    }

    // pool finalize -> gh = graph_emb @ W1b.T
    pool_fin_k<<<gGH, TPB>>>();
    mma_gemm_k<128,0,false><<<gGg, TPB, SMB>>>(p_gsum, 128, hw1 + 128, 256, nullptr, p_gh, GG);

    // physics MLP part 1: t1 = silu(h@pw1.T+pb1)  (fp16)
    mma_gemm_k<128,2,true><<<gGm, TPB, SMB>>>(p_h, 128, pw1, 128, pb1, p_t1, NN);

    // head (phys2 folded in): out[row] = b2 + silu([h;t1]@[W1a_h;Wc].T + c2 + gh[batch]) . w2
    head_gemm_k<<<gGm, TPB, SMB>>>(hw1, hw2, batch, out);
}

// round 10
// speedup vs baseline: 3.6450x; 1.1319x over previous
#include <cuda_runtime.h>
#include <cuda_fp16.h>
#include <cstdint>

#define NN 200000
#define EE 600000
#define GG 8192
#define HH 128
#define NB 196            // scan blocks: 196*1024 >= NN

// weight scratch offsets (floats)
#define WOFF_INW  0
#define WOFF_CONV 8192
#define WOFF_PW1  73728
#define WOFF_HW1  90112
#define WOFF_PW2T 122880
#define WTOT      139264

// ---------------- scratch (device globals: allocation-free) ----------------
__device__ float  g_h  [(size_t)NN*HH];     // residual stream (tf32-rounded fp32)
__device__ float  g_t1 [(size_t)NN*HH];     // phys1 output (tf32-rounded fp32)
__device__ __half g_hw [(size_t)NN*HH];     // conv outputs pre-scaled by dis (fp16)
__device__ float  g_dis[NN];
__device__ float  g_gsum[(size_t)GG*HH];
__device__ float  g_cnt[GG];
__device__ float  g_gh [(size_t)GG*HH];
__device__ float  g_wc  [HH*HH];
__device__ float  g_c2  [HH];
__device__ float  g_wr  [WTOT];             // tf32-rounded weights
// CSR
__device__ int g_deg[NN];
__device__ int g_fill[NN];
__device__ int g_rowptr[NN];
__device__ int g_csrc[EE];
__device__ int g_bsum[256];
__device__ int g_boff[256];

// ---------------- small helpers ----------------
__device__ __forceinline__ float4 ld4(const float* p){ return *reinterpret_cast<const float4*>(p); }
__device__ __forceinline__ void  st4(float* p, float4 v){ *reinterpret_cast<float4*>(p) = v; }
__device__ __forceinline__ void ldh4(const __half* p, float& x, float& y, float& z, float& w){
    uint2 u = *reinterpret_cast<const uint2*>(p);
    float2 f0 = __half22float2(*reinterpret_cast<__half2*>(&u.x));
    float2 f1 = __half22float2(*reinterpret_cast<__half2*>(&u.y));
    x = f0.x; y = f0.y; z = f1.x; w = f1.y;
}
__device__ __forceinline__ float siluf(float x){ return x / (1.f + __expf(-x)); }
__device__ __forceinline__ float wredsum(float v){
#pragma unroll
    for (int o = 16; o; o >>= 1) v += __shfl_xor_sync(0xffffffffu, v, o);
    return v;
}
__device__ __forceinline__ uint32_t f2tf32(float f){
    uint32_t u;
    asm("cvt.rna.tf32.f32 %0, %1;" : "=r"(u) : "f"(f));
    return u;
}
__device__ __forceinline__ float tf32r(float f){ return __uint_as_float(f2tf32(f)); }
__device__ __forceinline__ uint32_t smem_u32(const void* p){
    uint32_t a;
    asm("{ .reg .u64 t; cvta.to.shared.u64 t, %1; cvt.u32.u64 %0, t; }" : "=r"(a) : "l"(p));
    return a;
}
__device__ __forceinline__ void cpa16(uint32_t sa, const float* gp, uint32_t sz){
    asm volatile("cp.async.cg.shared.global [%0], [%1], 16, %2;" :: "r"(sa), "l"(gp), "r"(sz));
}
__device__ __forceinline__ void mma1688(float* d, const uint32_t* a, const uint32_t* b){
    asm volatile("mma.sync.aligned.m16n8k8.row.col.f32.tf32.tf32.f32 "
        "{%0,%1,%2,%3}, {%4,%5,%6,%7}, {%8,%9}, {%0,%1,%2,%3};"
        : "+f"(d[0]), "+f"(d[1]), "+f"(d[2]), "+f"(d[3])
        : "r"(a[0]), "r"(a[1]), "r"(a[2]), "r"(a[3]), "r"(b[0]), "r"(b[1]));
}

// ---------------- init (deg/fill zero, out=b2, pool zero) ----------------
__global__ void init_k(float* __restrict__ out, const float* __restrict__ b2){
    int i = blockIdx.x*blockDim.x + threadIdx.x;
    if (i < NN) { g_deg[i] = 0; g_fill[i] = 0; out[i] = b2[0]; }
    if (i < GG*HH) g_gsum[i] = 0.f;
    if (i < GG)    g_cnt[i]  = 0.f;
}

// ---------------- CSR build ----------------
__global__ void csr_hist_k(const int* __restrict__ dst){
    int e = blockIdx.x*blockDim.x + threadIdx.x;
    if (e < EE) atomicAdd(&g_deg[dst[e]], 1);
}
__global__ __launch_bounds__(256) void csr_scan1_k(){
    __shared__ int ss[256];
    const int tid = threadIdx.x;
    const int i0  = blockIdx.x*1024 + tid*4;
    int v[4];
#pragma unroll
    for (int q = 0; q < 4; q++) v[q] = (i0+q < NN) ? g_deg[i0+q] : 0;
    int tsum = v[0]+v[1]+v[2]+v[3];
    ss[tid] = tsum; __syncthreads();
#pragma unroll
    for (int off = 1; off < 256; off <<= 1) {
        int t = (tid >= off) ? ss[tid-off] : 0;
        __syncthreads();
        ss[tid] += t;
        __syncthreads();
    }
    if (tid == 255) g_bsum[blockIdx.x] = ss[255];
    int run = ss[tid] - tsum;
#pragma unroll
    for (int q = 0; q < 4; q++) {
        if (i0+q < NN) { g_rowptr[i0+q] = run; run += v[q]; }
    }
}
__global__ __launch_bounds__(256) void csr_scan2_k(){
    __shared__ int ss[256];
    const int tid = threadIdx.x;
    int v = (tid < NB) ? g_bsum[tid] : 0;
    ss[tid] = v; __syncthreads();
#pragma unroll
    for (int off = 1; off < 256; off <<= 1) {
        int t = (tid >= off) ? ss[tid-off] : 0;
        __syncthreads();
        ss[tid] += t;
        __syncthreads();
    }
    if (tid < NB) g_boff[tid] = ss[tid] - v;   // exclusive
}
__global__ void csr_scan3_k(){
    int i = blockIdx.x*blockDim.x + threadIdx.x;
    if (i < NN) {
        g_rowptr[i] += g_boff[i >> 10];
        g_dis[i] = rsqrtf((float)g_deg[i] + 1.0f);
    }
}
__global__ void csr_fill_k(const int* __restrict__ src, const int* __restrict__ dst){
    int e = blockIdx.x*blockDim.x + threadIdx.x;
    if (e < EE) {
        int d = dst[e];
        int pos = g_rowptr[d] + atomicAdd(&g_fill[d], 1);
        g_csrc[pos] = src[e];
    }
}

// ---------------- weight prep: tf32-round all GEMM weights ------------------
__global__ void prep_w_k(const float* __restrict__ in_w, const float* __restrict__ conv_w,
                         const float* __restrict__ pw1, const float* __restrict__ hw1,
                         const float* __restrict__ pw2){
    int i = blockIdx.x*blockDim.x + threadIdx.x;
    if (i < 8192)        g_wr[WOFF_INW  + i] = tf32r(in_w[i]);
    else if (i < 73728)  { int j = i-8192;   g_wr[WOFF_CONV + j] = tf32r(conv_w[j]); }
    else if (i < 90112)  { int j = i-73728;  g_wr[WOFF_PW1  + j] = tf32r(pw1[j]); }
    else if (i < 122880) { int j = i-90112;  g_wr[WOFF_HW1  + j] = tf32r(hw1[j]); }
    else if (i < WTOT)   { int j = i-122880; int r = j>>7, c = j&127;
                           g_wr[WOFF_PW2T + c*HH + r] = tf32r(pw2[j]); }
}
__global__ void c2_k(const float* __restrict__ hw1, const float* __restrict__ pb2,
                     const float* __restrict__ hb1){
    int i = threadIdx.x;
    float s = 0.f;
    for (int k = 0; k < HH; k++) s = fmaf(hw1[i*256 + k], pb2[k], s);
    g_c2[i] = s + hb1[i];
}

// ---------------- TF32 tensor-core GEMM (cp.async 2-stage pipeline) ----------
// out[M,128] = A[M,KT] @ W[128,KT]^T  (A row stride lda, W row stride ldw)
// EPI 0: out = acc (+bias) ; EPI 1: conv (out_h = half(acc*dis[row])) ;
// EPI 2: out = silu(acc + bias)
// CVTA: A in global is raw fp32 -> convert fragments to tf32 after LDS
// ROUND: tf32-round fp32 outputs (so they can feed later GEMMs raw)
template<int KT, int EPI, bool OUTH, bool CVTA, bool ROUND>
__global__ __launch_bounds__(256, 2) void mma_gemm_k(
    const float* __restrict__ A, int lda,
    const float* __restrict__ W, int ldw, const float* __restrict__ bias,
    void* __restrict__ outv, int M)
{
    constexpr int KC = 32, LDSN = 36, NC = KT / KC;
    constexpr int BUF = 128 * LDSN;
    extern __shared__ float smem[];

    const int tid = threadIdx.x, wid = tid >> 5, lid = tid & 31;
    const int wm = wid & 3, wn = wid >> 2;
    const int g  = lid >> 2, t = lid & 3;
    const int brow = blockIdx.x * 128;

    float acc[2][8][4];
#pragma unroll
    for (int mt = 0; mt < 2; mt++)
#pragma unroll
        for (int nt = 0; nt < 8; nt++)
#pragma unroll
            for (int q = 0; q < 4; q++) acc[mt][nt][q] = 0.f;

#define ISSUE(ci) do {                                                        \
        int _st = (ci) & 1;                                                   \
        float* Ad = smem + _st*BUF;                                           \
        float* Wd = smem + 2*BUF + _st*BUF;                                   \
        _Pragma("unroll")                                                     \
        for (int f = tid; f < 1024; f += 256) {                               \
            int row = f >> 3, kq = (f & 7) * 4;                               \
            int gr = brow + row;                                              \
            cpa16(smem_u32(Ad + row*LDSN + kq),                               \
                  A + (size_t)gr*lda + (ci)*KC + kq, (gr < M) ? 16u : 0u);    \
        }                                                                     \
        _Pragma("unroll")                                                     \
        for (int f = tid; f < 1024; f += 256) {                               \
            int n = f >> 3, kq = (f & 7) * 4;                                 \
            cpa16(smem_u32(Wd + n*LDSN + kq),                                 \
                  W + (size_t)n*ldw + (ci)*KC + kq, 16u);                     \
        }                                                                     \
        asm volatile("cp.async.commit_group;");                               \
    } while(0)

    ISSUE(0);
#pragma unroll
    for (int ci = 0; ci < NC; ci++) {
        if (ci + 1 < NC) { ISSUE(ci + 1); asm volatile("cp.async.wait_group 1;"); }
        else             { asm volatile("cp.async.wait_group 0;"); }
        __syncthreads();
        const float* As = smem + (ci & 1)*BUF;
        const float* Ws = smem + 2*BUF + (ci & 1)*BUF;
#pragma unroll
        for (int ks = 0; ks < KC/8; ks++) {
            const int kk = ks*8;
            uint32_t a[2][4], b[8][2];
#pragma unroll
            for (int mt = 0; mt < 2; mt++) {
                const float* ap = As + (wm*32 + mt*16 + g)*LDSN + kk + t;
                a[mt][0] = __float_as_uint(ap[0]);
                a[mt][1] = __float_as_uint(ap[8*LDSN]);
                a[mt][2] = __float_as_uint(ap[4]);
                a[mt][3] = __float_as_uint(ap[8*LDSN + 4]);
                if (CVTA) {
#pragma unroll
                    for (int q = 0; q < 4; q++) a[mt][q] = f2tf32(__uint_as_float(a[mt][q]));
                }
            }
#pragma unroll
            for (int nt = 0; nt < 8; nt++) {
                const float* bp = Ws + (wn*64 + nt*8 + g)*LDSN + kk + t;
                b[nt][0] = __float_as_uint(bp[0]);
                b[nt][1] = __float_as_uint(bp[4]);
            }
#pragma unroll
            for (int mt = 0; mt < 2; mt++)
#pragma unroll
                for (int nt = 0; nt < 8; nt++)
                    mma1688(acc[mt][nt], a[mt], b[nt]);
        }
        __syncthreads();
    }
#undef ISSUE

    float*  outf = (float*) outv;
    __half* outh = (__half*)outv;
#pragma unroll
    for (int mt = 0; mt < 2; mt++) {
#pragma unroll
        for (int half = 0; half < 2; half++) {
            int row = brow + wm*32 + mt*16 + g + half*8;
            if (row >= M) continue;
            size_t ro = (size_t)row*HH;
            float dsc = (EPI == 1) ? g_dis[row] : 0.f;
#pragma unroll
            for (int nt = 0; nt < 8; nt++) {
                int col = wn*64 + nt*8 + t*2;
                float v0 = acc[mt][nt][half*2 + 0];
                float v1 = acc[mt][nt][half*2 + 1];
                if (EPI == 0) {
                    if (bias) { v0 += bias[col]; v1 += bias[col+1]; }
                } else if (EPI == 1) {
                    v0 *= dsc; v1 *= dsc;
                } else if (EPI == 2) {
                    v0 = siluf(v0 + bias[col]); v1 = siluf(v1 + bias[col+1]);
                }
                if (ROUND) { v0 = tf32r(v0); v1 = tf32r(v1); }
                if (OUTH) {
                    *reinterpret_cast<__half2*>(outh + ro + col) = __floats2half2_rn(v0, v1);
                } else {
                    *reinterpret_cast<float2*>(outf + ro + col) = make_float2(v0, v1);
                }
            }
        }
    }
}

// ---------------- head GEMM (K=256 split: [h ; t1], W split: [W1a_h ; Wc]) ---
// hid = silu(acc + c2 + gh[batch]) ; out[row] += hid . w2  (out pre-init to b2)
__global__ __launch_bounds__(256, 2) void head_gemm_k(
    const float* __restrict__ w2, const int* __restrict__ batch,
    float* __restrict__ out)
{
    constexpr int KC = 32, LDSN = 36, NC = 8;
    constexpr int BUF = 128 * LDSN;
    extern __shared__ float smem[];

    const int tid = threadIdx.x, wid = tid >> 5, lid = tid & 31;
    const int wm = wid & 3, wn = wid >> 2;
    const int g  = lid >> 2, t = lid & 3;
    const int brow = blockIdx.x * 128;

    float acc[2][8][4];
#pragma unroll
    for (int mt = 0; mt < 2; mt++)
#pragma unroll
        for (int nt = 0; nt < 8; nt++)
#pragma unroll
            for (int q = 0; q < 4; q++) acc[mt][nt][q] = 0.f;

#define HISSUE(ci) do {                                                       \
        int _st = (ci) & 1;                                                   \
        float* Ad = smem + _st*BUF;                                           \
        float* Wd = smem + 2*BUF + _st*BUF;                                   \
        const float* Ap = ((ci) < 4) ? g_h : g_t1;                            \
        int _ka = ((ci)*KC) & 127;                                            \
        _Pragma("unroll")                                                     \
        for (int f = tid; f < 1024; f += 256) {                               \
            int row = f >> 3, kq = (f & 7) * 4;                               \
            int gr = brow + row;                                              \
            cpa16(smem_u32(Ad + row*LDSN + kq),                               \
                  Ap + (size_t)gr*HH + _ka + kq, (gr < NN) ? 16u : 0u);       \
        }                                                                     \
        _Pragma("unroll")                                                     \
        for (int f = tid; f < 1024; f += 256) {                               \
            int n = f >> 3, kq = (f & 7) * 4;                                 \
            const float* gp = ((ci) < 4)                                      \
                ? g_wr + WOFF_HW1 + (size_t)n*256 + (ci)*KC + kq              \
                : g_wc + (size_t)n*HH + _ka + kq;                             \
            cpa16(smem_u32(Wd + n*LDSN + kq), gp, 16u);                       \
        }                                                                     \
        asm volatile("cp.async.commit_group;");                               \
    } while(0)

    HISSUE(0);
#pragma unroll
    for (int ci = 0; ci < NC; ci++) {
        if (ci + 1 < NC) { HISSUE(ci + 1); asm volatile("cp.async.wait_group 1;"); }
        else             { asm volatile("cp.async.wait_group 0;"); }
        __syncthreads();
        const float* As = smem + (ci & 1)*BUF;
        const float* Ws = smem + 2*BUF + (ci & 1)*BUF;
#pragma unroll
        for (int ks = 0; ks < KC/8; ks++) {
            const int kk = ks*8;
            uint32_t a[2][4], b[8][2];
#pragma unroll
            for (int mt = 0; mt < 2; mt++) {
                const float* ap = As + (wm*32 + mt*16 + g)*LDSN + kk + t;
                a[mt][0] = __float_as_uint(ap[0]);
                a[mt][1] = __float_as_uint(ap[8*LDSN]);
                a[mt][2] = __float_as_uint(ap[4]);
                a[mt][3] = __float_as_uint(ap[8*LDSN + 4]);
            }
#pragma unroll
            for (int nt = 0; nt < 8; nt++) {
                const float* bp = Ws + (wn*64 + nt*8 + g)*LDSN + kk + t;
                b[nt][0] = __float_as_uint(bp[0]);
                b[nt][1] = __float_as_uint(bp[4]);
            }
#pragma unroll
            for (int mt = 0; mt < 2; mt++)
#pragma unroll
                for (int nt = 0; nt < 8; nt++)
                    mma1688(acc[mt][nt], a[mt], b[nt]);
        }
        __syncthreads();
    }
#undef HISSUE

#pragma unroll
    for (int mt = 0; mt < 2; mt++) {
#pragma unroll
        for (int half = 0; half < 2; half++) {
            int row = brow + wm*32 + mt*16 + g + half*8;
            float partial = 0.f;
            if (row < NN) {
                const float* ghrow = g_gh + (size_t)batch[row]*HH;
#pragma unroll
                for (int nt = 0; nt < 8; nt++) {
                    int col = wn*64 + nt*8 + t*2;
                    float v0 = siluf(acc[mt][nt][half*2+0] + g_c2[col]   + ghrow[col]);
                    float v1 = siluf(acc[mt][nt][half*2+1] + g_c2[col+1] + ghrow[col+1]);
                    partial = fmaf(v0, w2[col], partial);
                    partial = fmaf(v1, w2[col+1], partial);
                }
            }
            partial += __shfl_xor_sync(0xffffffffu, partial, 1);
            partial += __shfl_xor_sync(0xffffffffu, partial, 2);
            if (t == 0 && row < NN)
                asm volatile("red.global.add.f32 [%0], %1;" :: "l"(out + row), "f"(partial) : "memory");
        }
    }
}

// ---- fused neighbor-gather + self-loop + bias + silu + LN + residual (+pool)
// hwsc rows are pre-scaled by dis[src]; agg = di * (hwsc[row] + sum hwsc[s]) + b
template<bool POOL>
__global__ __launch_bounds__(256) void gather_ln_k(const float* __restrict__ bias,
                                                   const float* __restrict__ lng,
                                                   const float* __restrict__ lnb,
                                                   const int* __restrict__ batch)
{
    int row = blockIdx.x * 8 + (threadIdx.x >> 5);
    if (row >= NN) return;
    int lane = threadIdx.x & 31;
    const int cnt   = g_deg[row];
    const int start = g_rowptr[row];
    const float di  = g_dis[row];
    size_t off = (size_t)row*HH + lane*4;

    float ax, ay, az, aw;
    ldh4(g_hw + off, ax, ay, az, aw);      // self term (already *di)

    for (int j = 0; j < cnt; j++) {
        int s = g_csrc[start + j];
        float vx, vy, vz, vw;
        ldh4(g_hw + (size_t)s*HH + lane*4, vx, vy, vz, vw);
        ax += vx; ay += vy; az += vz; aw += vw;
    }

    float4 b4 = ld4(bias + lane*4);
    ax = fmaf(ax, di, b4.x); ay = fmaf(ay, di, b4.y);
    az = fmaf(az, di, b4.z); aw = fmaf(aw, di, b4.w);

    float s0 = siluf(ax), s1 = siluf(ay), s2 = siluf(az), s3 = siluf(aw);
    float sum = wredsum(s0+s1+s2+s3);
    float sq  = wredsum(s0*s0 + s1*s1 + s2*s2 + s3*s3);
    float mu  = sum * (1.f/128.f);
    float var = sq * (1.f/128.f) - mu*mu;
    float inv = rsqrtf(var + 1e-5f);
    float4 h = ld4(g_h + off);
    int c = lane*4;
    h.x = tf32r(h.x + (s0 - mu)*inv*lng[c+0] + lnb[c+0]);
    h.y = tf32r(h.y + (s1 - mu)*inv*lng[c+1] + lnb[c+1]);
    h.z = tf32r(h.z + (s2 - mu)*inv*lng[c+2] + lnb[c+2]);
    h.w = tf32r(h.w + (s3 - mu)*inv*lng[c+3] + lnb[c+3]);
    st4(g_h + off, h);

    if (POOL) {
        int b = batch[row];
        float* p = g_gsum + (size_t)b*HH + lane*4;
        asm volatile("red.global.add.v4.f32 [%0], {%1,%2,%3,%4};"
                     :: "l"(p), "f"(h.x), "f"(h.y), "f"(h.z), "f"(h.w) : "memory");
        if (lane == 0) atomicAdd(&g_cnt[b], 1.0f);
    }
}

// ---------------- pool finalize (tf32-rounded: feeds gh GEMM) ---------------
__global__ void pool_fin_k(){
    int i = blockIdx.x*blockDim.x + threadIdx.x;
    if (i < GG*HH) {
        int g = i / HH;
        g_gsum[i] = tf32r(g_gsum[i] / fmaxf(g_cnt[g], 1.0f));
    }
}

// ---------------- launch ----------------
extern "C" void kernel_launch(void* const* d_in, const int* in_sizes, int n_in,
                              void* d_out, int out_size)
{
    const float* x      = (const float*)d_in[0];
    const int*   ei     = (const int*)  d_in[1];
    const int*   src    = ei;
    const int*   dst    = ei + EE;
    const int*   batch  = (const int*)  d_in[2];
    const float* in_w   = (const float*)d_in[3];
    const float* in_b   = (const float*)d_in[4];
    const float* conv_w = (const float*)d_in[5];
    const float* conv_b = (const float*)d_in[6];
    const float* ln_g   = (const float*)d_in[7];
    const float* ln_b   = (const float*)d_in[8];
    const float* pw1    = (const float*)d_in[9];
    const float* pb1    = (const float*)d_in[10];
    const float* pw2    = (const float*)d_in[11];
    const float* pb2    = (const float*)d_in[12];
    const float* hw1    = (const float*)d_in[13];
    const float* hb1    = (const float*)d_in[14];
    const float* hw2    = (const float*)d_in[15];
    const float* hb2    = (const float*)d_in[16];
    float* out = (float*)d_out;

    float *p_h, *p_t1, *p_gsum, *p_gh, *p_wc, *p_wr;
    __half *p_hw;
    cudaGetSymbolAddress((void**)&p_h,    g_h);
    cudaGetSymbolAddress((void**)&p_t1,   g_t1);
    cudaGetSymbolAddress((void**)&p_hw,   g_hw);
    cudaGetSymbolAddress((void**)&p_gsum, g_gsum);
    cudaGetSymbolAddress((void**)&p_gh,   g_gh);
    cudaGetSymbolAddress((void**)&p_wc,   g_wc);
    cudaGetSymbolAddress((void**)&p_wr,   g_wr);

    const int TPB = 256;
    const int gI  = (GG*HH + TPB - 1) / TPB;     // covers NN too
    const int gN  = (NN + TPB - 1) / TPB;
    const int gE  = (EE + TPB - 1) / TPB;
    const int gWN = (NN + 7) / 8;
    const int gGm = (NN + 127) / 128;
    const int gGg = GG / 128;
    const int gW  = (WTOT + TPB - 1) / TPB;

    const int SMB = 4 * 128 * 36 * 4;   // 73728 B dynamic smem (2-stage A+W)
    cudaFuncSetAttribute(mma_gemm_k< 64,0,false,true ,true >, cudaFuncAttributeMaxDynamicSharedMemorySize, SMB);
    cudaFuncSetAttribute(mma_gemm_k<128,0,false,false,true >, cudaFuncAttributeMaxDynamicSharedMemorySize, SMB);
    cudaFuncSetAttribute(mma_gemm_k<128,0,false,false,false>, cudaFuncAttributeMaxDynamicSharedMemorySize, SMB);
    cudaFuncSetAttribute(mma_gemm_k<128,1,true ,false,false>, cudaFuncAttributeMaxDynamicSharedMemorySize, SMB);
    cudaFuncSetAttribute(mma_gemm_k<128,2,false,false,true >, cudaFuncAttributeMaxDynamicSharedMemorySize, SMB);
    cudaFuncSetAttribute(head_gemm_k,                         cudaFuncAttributeMaxDynamicSharedMemorySize, SMB);

    // init + CSR build + weight prep
    init_k     <<<gI, TPB>>>(out, hb2);
    csr_hist_k <<<gE, TPB>>>(dst);
    csr_scan1_k<<<NB, TPB>>>();
    csr_scan2_k<<<1,  TPB>>>();
    csr_scan3_k<<<gN, TPB>>>();
    csr_fill_k <<<gE, TPB>>>(src, dst);
    prep_w_k   <<<gW, TPB>>>(in_w, conv_w, pw1, hw1, pw2);

    // Wc = W1a_h @ pw2 (rounded out) ; c2
    mma_gemm_k<128,0,false,false,true><<<1, TPB, SMB>>>(p_wr + WOFF_HW1, 256,
                                                        p_wr + WOFF_PW2T, 128, nullptr, p_wc, 128);
    c2_k<<<1, 128>>>(hw1, pb2, hb1);

    // input projection: h = x @ in_w.T + in_b (rounded)
    mma_gemm_k<64,0,false,true,true><<<gGm, TPB, SMB>>>(x, 64, p_wr + WOFF_INW, 64,
                                                        in_b, p_h, NN);

    // GCN layers: hwsc = (h @ W.T)*dis (fp16) ; h += LN(silu(di*gather + bias))
    for (int l = 0; l < 4; l++) {
        mma_gemm_k<128,1,true,false,false><<<gGm, TPB, SMB>>>(p_h, 128,
                                                              p_wr + WOFF_CONV + (size_t)l*HH*HH, 128,
                                                              nullptr, p_hw, NN);
        if (l < 3) gather_ln_k<false><<<gWN, TPB>>>(conv_b + l*HH, ln_g + l*HH, ln_b + l*HH, batch);
        else       gather_ln_k<true ><<<gWN, TPB>>>(conv_b + l*HH, ln_g + l*HH, ln_b + l*HH, batch);
    }

    // pool finalize -> gh = graph_emb @ W1b.T
    pool_fin_k<<<gI, TPB>>>();
    mma_gemm_k<128,0,false,false,false><<<gGg, TPB, SMB>>>(p_gsum, 128,
                                                           p_wr + WOFF_HW1 + 128, 256,
                                                           nullptr, p_gh, GG);

    // physics MLP part 1: t1 = silu(h@pw1.T+pb1) (rounded fp32)
    mma_gemm_k<128,2,false,false,true><<<gGm, TPB, SMB>>>(p_h, 128, p_wr + WOFF_PW1, 128,
                                                          pb1, p_t1, NN);

    // head: out[row] = b2 + silu([h;t1]@[W1a_h;Wc].T + c2 + gh[batch]) . w2
    head_gemm_k<<<gGm, TPB, SMB>>>(hw2, batch, out);
}

// round 11
// speedup vs baseline: 3.7234x; 1.0215x over previous
#include <cuda_runtime.h>
#include <cuda_fp16.h>
#include <cstdint>

#define NN 200000
#define EE 600000
#define GG 8192
#define HH 128
#define NB 196            // scan blocks: 196*1024 >= NN

// weight scratch offsets (floats)
#define WOFF_INW  0
#define WOFF_CONV 8192
#define WOFF_PW1  73728
#define WOFF_HW1  90112
#define WOFF_PW2T 122880
#define WTOT      139264

// ---------------- scratch (device globals: allocation-free) ----------------
__device__ float  g_h  [(size_t)NN*HH];     // residual stream (tf32-rounded fp32)
__device__ float  g_t1 [(size_t)NN*HH];     // phys1 output (tf32-rounded fp32)
__device__ __half g_hw [(size_t)NN*HH];     // conv outputs pre-scaled by dis (fp16)
__device__ float  g_dis[NN];
__device__ float  g_gsum[(size_t)GG*HH];
__device__ float  g_cnt[GG];
__device__ float  g_gh [(size_t)GG*HH];
__device__ float  g_wc  [HH*HH];
__device__ float  g_c2  [HH];
__device__ float  g_wr  [WTOT];             // tf32-rounded weights
// CSR
__device__ int g_deg[NN];
__device__ int g_fill[NN];
__device__ int g_rowptr[NN];
__device__ int g_csrc[EE];
__device__ int g_bsum[256];
__device__ int g_boff[256];

// ---------------- small helpers ----------------
__device__ __forceinline__ float4 ld4(const float* p){ return *reinterpret_cast<const float4*>(p); }
__device__ __forceinline__ void  st4(float* p, float4 v){ *reinterpret_cast<float4*>(p) = v; }
__device__ __forceinline__ float siluf(float x){ return x / (1.f + __expf(-x)); }
__device__ __forceinline__ uint32_t f2tf32(float f){
    uint32_t u;
    asm("cvt.rna.tf32.f32 %0, %1;" : "=r"(u) : "f"(f));
    return u;
}
__device__ __forceinline__ float tf32r(float f){ return __uint_as_float(f2tf32(f)); }
__device__ __forceinline__ uint32_t smem_u32(const void* p){
    uint32_t a;
    asm("{ .reg .u64 t; cvta.to.shared.u64 t, %1; cvt.u32.u64 %0, t; }" : "=r"(a) : "l"(p));
    return a;
}
__device__ __forceinline__ void cpa16(uint32_t sa, const float* gp, uint32_t sz){
    asm volatile("cp.async.cg.shared.global [%0], [%1], 16, %2;" :: "r"(sa), "l"(gp), "r"(sz));
}
__device__ __forceinline__ void mma1688(float* d, const uint32_t* a, const uint32_t* b){
    asm volatile("mma.sync.aligned.m16n8k8.row.col.f32.tf32.tf32.f32 "
        "{%0,%1,%2,%3}, {%4,%5,%6,%7}, {%8,%9}, {%0,%1,%2,%3};"
        : "+f"(d[0]), "+f"(d[1]), "+f"(d[2]), "+f"(d[3])
        : "r"(a[0]), "r"(a[1]), "r"(a[2]), "r"(a[3]), "r"(b[0]), "r"(b[1]));
}
// accumulate 8 fp16 (one uint4) into 8 fp32
__device__ __forceinline__ void acc8(float* a, uint4 u){
    float2 f;
    f = __half22float2(*reinterpret_cast<__half2*>(&u.x)); a[0]+=f.x; a[1]+=f.y;
    f = __half22float2(*reinterpret_cast<__half2*>(&u.y)); a[2]+=f.x; a[3]+=f.y;
    f = __half22float2(*reinterpret_cast<__half2*>(&u.z)); a[4]+=f.x; a[5]+=f.y;
    f = __half22float2(*reinterpret_cast<__half2*>(&u.w)); a[6]+=f.x; a[7]+=f.y;
}

// ---------------- init (deg/fill zero, out=b2, pool zero) ----------------
__global__ void init_k(float* __restrict__ out, const float* __restrict__ b2){
    int i = blockIdx.x*blockDim.x + threadIdx.x;
    if (i < NN) { g_deg[i] = 0; g_fill[i] = 0; out[i] = b2[0]; }
    if (i < GG*HH) g_gsum[i] = 0.f;
    if (i < GG)    g_cnt[i]  = 0.f;
}

// ---------------- CSR build ----------------
__global__ void csr_hist_k(const int* __restrict__ dst){
    int e = blockIdx.x*blockDim.x + threadIdx.x;
    if (e < EE) atomicAdd(&g_deg[dst[e]], 1);
}
__global__ __launch_bounds__(256) void csr_scan1_k(){
    __shared__ int ss[256];
    const int tid = threadIdx.x;
    const int i0  = blockIdx.x*1024 + tid*4;
    int v[4];
#pragma unroll
    for (int q = 0; q < 4; q++) v[q] = (i0+q < NN) ? g_deg[i0+q] : 0;
    int tsum = v[0]+v[1]+v[2]+v[3];
    ss[tid] = tsum; __syncthreads();
#pragma unroll
    for (int off = 1; off < 256; off <<= 1) {
        int t = (tid >= off) ? ss[tid-off] : 0;
        __syncthreads();
        ss[tid] += t;
        __syncthreads();
    }
    if (tid == 255) g_bsum[blockIdx.x] = ss[255];
    int run = ss[tid] - tsum;
#pragma unroll
    for (int q = 0; q < 4; q++) {
        if (i0+q < NN) { g_rowptr[i0+q] = run; run += v[q]; }
    }
}
__global__ __launch_bounds__(256) void csr_scan2_k(){
    __shared__ int ss[256];
    const int tid = threadIdx.x;
    int v = (tid < NB) ? g_bsum[tid] : 0;
    ss[tid] = v; __syncthreads();
#pragma unroll
    for (int off = 1; off < 256; off <<= 1) {
        int t = (tid >= off) ? ss[tid-off] : 0;
        __syncthreads();
        ss[tid] += t;
        __syncthreads();
    }
    if (tid < NB) g_boff[tid] = ss[tid] - v;   // exclusive
}
__global__ void csr_scan3_k(){
    int i = blockIdx.x*blockDim.x + threadIdx.x;
    if (i < NN) {
        g_rowptr[i] += g_boff[i >> 10];
        g_dis[i] = rsqrtf((float)g_deg[i] + 1.0f);
    }
}
__global__ void csr_fill_k(const int* __restrict__ src, const int* __restrict__ dst){
    int e = blockIdx.x*blockDim.x + threadIdx.x;
    if (e < EE) {
        int d = dst[e];
        int pos = g_rowptr[d] + atomicAdd(&g_fill[d], 1);
        g_csrc[pos] = src[e];
    }
}

// ---------------- weight prep: tf32-round all GEMM weights ------------------
__global__ void prep_w_k(const float* __restrict__ in_w, const float* __restrict__ conv_w,
                         const float* __restrict__ pw1, const float* __restrict__ hw1,
                         const float* __restrict__ pw2){
    int i = blockIdx.x*blockDim.x + threadIdx.x;
    if (i < 8192)        g_wr[WOFF_INW  + i] = tf32r(in_w[i]);
    else if (i < 73728)  { int j = i-8192;   g_wr[WOFF_CONV + j] = tf32r(conv_w[j]); }
    else if (i < 90112)  { int j = i-73728;  g_wr[WOFF_PW1  + j] = tf32r(pw1[j]); }
    else if (i < 122880) { int j = i-90112;  g_wr[WOFF_HW1  + j] = tf32r(hw1[j]); }
    else if (i < WTOT)   { int j = i-122880; int r = j>>7, c = j&127;
                           g_wr[WOFF_PW2T + c*HH + r] = tf32r(pw2[j]); }
}
__global__ void c2_k(const float* __restrict__ hw1, const float* __restrict__ pb2,
                     const float* __restrict__ hb1){
    int i = threadIdx.x;
    float s = 0.f;
    for (int k = 0; k < HH; k++) s = fmaf(hw1[i*256 + k], pb2[k], s);
    g_c2[i] = s + hb1[i];
}

// ---------------- TF32 tensor-core GEMM (cp.async 2-stage pipeline) ----------
// out[M,128] = A[M,KT] @ W[128,KT]^T  (A row stride lda, W row stride ldw)
// EPI 0: out = acc (+bias) ; EPI 1: conv (out_h = half(acc*dis[row])) ;
// EPI 2: out = silu(acc + bias) ; EPI 3: out = acc / max(g_cnt[row],1)  (pool)
// CVTA: A in global is raw fp32 -> convert fragments to tf32 after LDS
// ROUND: tf32-round fp32 outputs (so they can feed later GEMMs raw)
template<int KT, int EPI, bool OUTH, bool CVTA, bool ROUND>
__global__ __launch_bounds__(256, 2) void mma_gemm_k(
    const float* __restrict__ A, int lda,
    const float* __restrict__ W, int ldw, const float* __restrict__ bias,
    void* __restrict__ outv, int M)
{
    constexpr int KC = 32, LDSN = 36, NC = KT / KC;
    constexpr int BUF = 128 * LDSN;
    extern __shared__ float smem[];

    const int tid = threadIdx.x, wid = tid >> 5, lid = tid & 31;
    const int wm = wid & 3, wn = wid >> 2;
    const int g  = lid >> 2, t = lid & 3;
    const int brow = blockIdx.x * 128;

    float acc[2][8][4];
#pragma unroll
    for (int mt = 0; mt < 2; mt++)
#pragma unroll
        for (int nt = 0; nt < 8; nt++)
#pragma unroll
            for (int q = 0; q < 4; q++) acc[mt][nt][q] = 0.f;

#define ISSUE(ci) do {                                                        \
        int _st = (ci) & 1;                                                   \
        float* Ad = smem + _st*BUF;                                           \
        float* Wd = smem + 2*BUF + _st*BUF;                                   \
        _Pragma("unroll")                                                     \
        for (int f = tid; f < 1024; f += 256) {                               \
            int row = f >> 3, kq = (f & 7) * 4;                               \
            int gr = brow + row;                                              \
            cpa16(smem_u32(Ad + row*LDSN + kq),                               \
                  A + (size_t)gr*lda + (ci)*KC + kq, (gr < M) ? 16u : 0u);    \
        }                                                                     \
        _Pragma("unroll")                                                     \
        for (int f = tid; f < 1024; f += 256) {                               \
            int n = f >> 3, kq = (f & 7) * 4;                                 \
            cpa16(smem_u32(Wd + n*LDSN + kq),                                 \
                  W + (size_t)n*ldw + (ci)*KC + kq, 16u);                     \
        }                                                                     \
        asm volatile("cp.async.commit_group;");                               \
    } while(0)

    ISSUE(0);
#pragma unroll
    for (int ci = 0; ci < NC; ci++) {
        if (ci + 1 < NC) { ISSUE(ci + 1); asm volatile("cp.async.wait_group 1;"); }
        else             { asm volatile("cp.async.wait_group 0;"); }
        __syncthreads();
        const float* As = smem + (ci & 1)*BUF;
        const float* Ws = smem + 2*BUF + (ci & 1)*BUF;
#pragma unroll
        for (int ks = 0; ks < KC/8; ks++) {
            const int kk = ks*8;
            uint32_t a[2][4], b[8][2];
#pragma unroll
            for (int mt = 0; mt < 2; mt++) {
                const float* ap = As + (wm*32 + mt*16 + g)*LDSN + kk + t;
                a[mt][0] = __float_as_uint(ap[0]);
                a[mt][1] = __float_as_uint(ap[8*LDSN]);
                a[mt][2] = __float_as_uint(ap[4]);
                a[mt][3] = __float_as_uint(ap[8*LDSN + 4]);
                if (CVTA) {
#pragma unroll
                    for (int q = 0; q < 4; q++) a[mt][q] = f2tf32(__uint_as_float(a[mt][q]));
                }
            }
#pragma unroll
            for (int nt = 0; nt < 8; nt++) {
                const float* bp = Ws + (wn*64 + nt*8 + g)*LDSN + kk + t;
                b[nt][0] = __float_as_uint(bp[0]);
                b[nt][1] = __float_as_uint(bp[4]);
            }
#pragma unroll
            for (int mt = 0; mt < 2; mt++)
#pragma unroll
                for (int nt = 0; nt < 8; nt++)
                    mma1688(acc[mt][nt], a[mt], b[nt]);
        }
        __syncthreads();
    }
#undef ISSUE

    float*  outf = (float*) outv;
    __half* outh = (__half*)outv;
#pragma unroll
    for (int mt = 0; mt < 2; mt++) {
#pragma unroll
        for (int half = 0; half < 2; half++) {
            int row = brow + wm*32 + mt*16 + g + half*8;
            if (row >= M) continue;
            size_t ro = (size_t)row*HH;
            float dsc = 0.f;
            if (EPI == 1) dsc = g_dis[row];
            if (EPI == 3) dsc = 1.f / fmaxf(g_cnt[row], 1.f);
#pragma unroll
            for (int nt = 0; nt < 8; nt++) {
                int col = wn*64 + nt*8 + t*2;
                float v0 = acc[mt][nt][half*2 + 0];
                float v1 = acc[mt][nt][half*2 + 1];
                if (EPI == 0) {
                    if (bias) { v0 += bias[col]; v1 += bias[col+1]; }
                } else if (EPI == 1 || EPI == 3) {
                    v0 *= dsc; v1 *= dsc;
                } else if (EPI == 2) {
                    v0 = siluf(v0 + bias[col]); v1 = siluf(v1 + bias[col+1]);
                }
                if (ROUND) { v0 = tf32r(v0); v1 = tf32r(v1); }
                if (OUTH) {
                    *reinterpret_cast<__half2*>(outh + ro + col) = __floats2half2_rn(v0, v1);
                } else {
                    *reinterpret_cast<float2*>(outf + ro + col) = make_float2(v0, v1);
                }
            }
        }
    }
}

// ---------------- head GEMM (K=256 split: [h ; t1], W split: [W1a_h ; Wc]) ---
// hid = silu(acc + c2 + gh[batch]) ; out[row] += hid . w2  (out pre-init to b2)
__global__ __launch_bounds__(256, 2) void head_gemm_k(
    const float* __restrict__ w2, const int* __restrict__ batch,
    float* __restrict__ out)
{
    constexpr int KC = 32, LDSN = 36, NC = 8;
    constexpr int BUF = 128 * LDSN;
    extern __shared__ float smem[];

    const int tid = threadIdx.x, wid = tid >> 5, lid = tid & 31;
    const int wm = wid & 3, wn = wid >> 2;
    const int g  = lid >> 2, t = lid & 3;
    const int brow = blockIdx.x * 128;

    float acc[2][8][4];
#pragma unroll
    for (int mt = 0; mt < 2; mt++)
#pragma unroll
        for (int nt = 0; nt < 8; nt++)
#pragma unroll
            for (int q = 0; q < 4; q++) acc[mt][nt][q] = 0.f;

#define HISSUE(ci) do {                                                       \
        int _st = (ci) & 1;                                                   \
        float* Ad = smem + _st*BUF;                                           \
        float* Wd = smem + 2*BUF + _st*BUF;                                   \
        const float* Ap = ((ci) < 4) ? g_h : g_t1;                            \
        int _ka = ((ci)*KC) & 127;                                            \
        _Pragma("unroll")                                                     \
        for (int f = tid; f < 1024; f += 256) {                               \
            int row = f >> 3, kq = (f & 7) * 4;                               \
            int gr = brow + row;                                              \
            cpa16(smem_u32(Ad + row*LDSN + kq),                               \
                  Ap + (size_t)gr*HH + _ka + kq, (gr < NN) ? 16u : 0u);       \
        }                                                                     \
        _Pragma("unroll")                                                     \
        for (int f = tid; f < 1024; f += 256) {                               \
            int n = f >> 3, kq = (f & 7) * 4;                                 \
            const float* gp = ((ci) < 4)                                      \
                ? g_wr + WOFF_HW1 + (size_t)n*256 + (ci)*KC + kq              \
                : g_wc + (size_t)n*HH + _ka + kq;                             \
            cpa16(smem_u32(Wd + n*LDSN + kq), gp, 16u);                       \
        }                                                                     \
        asm volatile("cp.async.commit_group;");                               \
    } while(0)

    HISSUE(0);
#pragma unroll
    for (int ci = 0; ci < NC; ci++) {
        if (ci + 1 < NC) { HISSUE(ci + 1); asm volatile("cp.async.wait_group 1;"); }
        else             { asm volatile("cp.async.wait_group 0;"); }
        __syncthreads();
        const float* As = smem + (ci & 1)*BUF;
        const float* Ws = smem + 2*BUF + (ci & 1)*BUF;
#pragma unroll
        for (int ks = 0; ks < KC/8; ks++) {
            const int kk = ks*8;
            uint32_t a[2][4], b[8][2];
#pragma unroll
            for (int mt = 0; mt < 2; mt++) {
                const float* ap = As + (wm*32 + mt*16 + g)*LDSN + kk + t;
                a[mt][0] = __float_as_uint(ap[0]);
                a[mt][1] = __float_as_uint(ap[8*LDSN]);
                a[mt][2] = __float_as_uint(ap[4]);
                a[mt][3] = __float_as_uint(ap[8*LDSN + 4]);
            }
#pragma unroll
            for (int nt = 0; nt < 8; nt++) {
                const float* bp = Ws + (wn*64 + nt*8 + g)*LDSN + kk + t;
                b[nt][0] = __float_as_uint(bp[0]);
                b[nt][1] = __float_as_uint(bp[4]);
            }
#pragma unroll
            for (int mt = 0; mt < 2; mt++)
#pragma unroll
                for (int nt = 0; nt < 8; nt++)
                    mma1688(acc[mt][nt], a[mt], b[nt]);
        }
        __syncthreads();
    }
#undef HISSUE

#pragma unroll
    for (int mt = 0; mt < 2; mt++) {
#pragma unroll
        for (int half = 0; half < 2; half++) {
            int row = brow + wm*32 + mt*16 + g + half*8;
            float partial = 0.f;
            if (row < NN) {
                const float* ghrow = g_gh + (size_t)batch[row]*HH;
#pragma unroll
                for (int nt = 0; nt < 8; nt++) {
                    int col = wn*64 + nt*8 + t*2;
                    float v0 = siluf(acc[mt][nt][half*2+0] + g_c2[col]   + ghrow[col]);
                    float v1 = siluf(acc[mt][nt][half*2+1] + g_c2[col+1] + ghrow[col+1]);
                    partial = fmaf(v0, w2[col], partial);
                    partial = fmaf(v1, w2[col+1], partial);
                }
            }
            partial += __shfl_xor_sync(0xffffffffu, partial, 1);
            partial += __shfl_xor_sync(0xffffffffu, partial, 2);
            if (t == 0 && row < NN)
                asm volatile("red.global.add.f32 [%0], %1;" :: "l"(out + row), "f"(partial) : "memory");
        }
    }
}

// ---- fused neighbor-gather + silu + LN + residual (+pool) ------------------
// half-warp (16 lanes) per node, 16B fp16 loads, neighbor loop unrolled x2.
// hwsc rows pre-scaled by dis[src]; agg = di*(hwsc[node] + sum hwsc[s]) + bias
template<bool POOL>
__global__ __launch_bounds__(256) void gather_ln_k(const float* __restrict__ bias,
                                                   const float* __restrict__ lng,
                                                   const float* __restrict__ lnb,
                                                   const int* __restrict__ batch)
{
    int node = blockIdx.x * 16 + (threadIdx.x >> 4);
    if (node >= NN) return;
    const int l16 = threadIdx.x & 15;
    const int c0  = l16 * 8;
    const int cnt   = g_deg[node];
    const int start = g_rowptr[node];
    const float di  = g_dis[node];
    const size_t off = (size_t)node*HH + c0;

    float a[8] = {0,0,0,0,0,0,0,0};
    acc8(a, *reinterpret_cast<const uint4*>(g_hw + off));   // self term (already *di)

    int j = 0;
    for (; j + 2 <= cnt; j += 2) {
        int s0 = g_csrc[start + j];
        int s1 = g_csrc[start + j + 1];
        uint4 u0 = *reinterpret_cast<const uint4*>(g_hw + (size_t)s0*HH + c0);
        uint4 u1 = *reinterpret_cast<const uint4*>(g_hw + (size_t)s1*HH + c0);
        acc8(a, u0);
        acc8(a, u1);
    }
    if (j < cnt) {
        int s = g_csrc[start + j];
        acc8(a, *reinterpret_cast<const uint4*>(g_hw + (size_t)s*HH + c0));
    }

    float4 b0 = ld4(bias + c0), b1 = ld4(bias + c0 + 4);
    float s[8];
    s[0] = siluf(fmaf(a[0], di, b0.x)); s[1] = siluf(fmaf(a[1], di, b0.y));
    s[2] = siluf(fmaf(a[2], di, b0.z)); s[3] = siluf(fmaf(a[3], di, b0.w));
    s[4] = siluf(fmaf(a[4], di, b1.x)); s[5] = siluf(fmaf(a[5], di, b1.y));
    s[6] = siluf(fmaf(a[6], di, b1.z)); s[7] = siluf(fmaf(a[7], di, b1.w));

    float sum = 0.f, sq = 0.f;
#pragma unroll
    for (int q = 0; q < 8; q++) { sum += s[q]; sq = fmaf(s[q], s[q], sq); }
#pragma unroll
    for (int o = 1; o < 16; o <<= 1) {
        sum += __shfl_xor_sync(0xffffffffu, sum, o);
        sq  += __shfl_xor_sync(0xffffffffu, sq,  o);
    }
    float mu  = sum * (1.f/128.f);
    float var = sq * (1.f/128.f) - mu*mu;
    float inv = rsqrtf(var + 1e-5f);

    float4 g0 = ld4(lng + c0), g1 = ld4(lng + c0 + 4);
    float4 e0 = ld4(lnb + c0), e1 = ld4(lnb + c0 + 4);
    float4 h0 = ld4(g_h + off), h1 = ld4(g_h + off + 4);
    h0.x = tf32r(h0.x + (s[0]-mu)*inv*g0.x + e0.x);
    h0.y = tf32r(h0.y + (s[1]-mu)*inv*g0.y + e0.y);
    h0.z = tf32r(h0.z + (s[2]-mu)*inv*g0.z + e0.z);
    h0.w = tf32r(h0.w + (s[3]-mu)*inv*g0.w + e0.w);
    h1.x = tf32r(h1.x + (s[4]-mu)*inv*g1.x + e1.x);
    h1.y = tf32r(h1.y + (s[5]-mu)*inv*g1.y + e1.y);
    h1.z = tf32r(h1.z + (s[6]-mu)*inv*g1.z + e1.z);
    h1.w = tf32r(h1.w + (s[7]-mu)*inv*g1.w + e1.w);
    st4(g_h + off, h0);
    st4(g_h + off + 4, h1);

    if (POOL) {
        int b = batch[node];
        float* p = g_gsum + (size_t)b*HH + c0;
        asm volatile("red.global.add.v4.f32 [%0], {%1,%2,%3,%4};"
                     :: "l"(p), "f"(h0.x), "f"(h0.y), "f"(h0.z), "f"(h0.w) : "memory");
        asm volatile("red.global.add.v4.f32 [%0], {%1,%2,%3,%4};"
                     :: "l"(p+4), "f"(h1.x), "f"(h1.y), "f"(h1.z), "f"(h1.w) : "memory");
        if (l16 == 0) atomicAdd(&g_cnt[b], 1.0f);
    }
}

// ---------------- launch ----------------
extern "C" void kernel_launch(void* const* d_in, const int* in_sizes, int n_in,
                              void* d_out, int out_size)
{
    const float* x      = (const float*)d_in[0];
    const int*   ei     = (const int*)  d_in[1];
    const int*   src    = ei;
    const int*   dst    = ei + EE;
    const int*   batch  = (const int*)  d_in[2];
    const float* in_w   = (const float*)d_in[3];
    const float* in_b   = (const float*)d_in[4];
    const float* conv_w = (const float*)d_in[5];
    const float* conv_b = (const float*)d_in[6];
    const float* ln_g   = (const float*)d_in[7];
    const float* ln_b   = (const float*)d_in[8];
    const float* pw1    = (const float*)d_in[9];
    const float* pb1    = (const float*)d_in[10];
    const float* pw2    = (const float*)d_in[11];
    const float* pb2    = (const float*)d_in[12];
    const float* hw1    = (const float*)d_in[13];
    const float* hb1    = (const float*)d_in[14];
    const float* hw2    = (const float*)d_in[15];
    const float* hb2    = (const float*)d_in[16];
    float* out = (float*)d_out;

    float *p_h, *p_t1, *p_gsum, *p_gh, *p_wc, *p_wr;
    __half *p_hw;
    cudaGetSymbolAddress((void**)&p_h,    g_h);
    cudaGetSymbolAddress((void**)&p_t1,   g_t1);
    cudaGetSymbolAddress((void**)&p_hw,   g_hw);
    cudaGetSymbolAddress((void**)&p_gsum, g_gsum);
    cudaGetSymbolAddress((void**)&p_gh,   g_gh);
    cudaGetSymbolAddress((void**)&p_wc,   g_wc);
    cudaGetSymbolAddress((void**)&p_wr,   g_wr);

    const int TPB = 256;
    const int gI  = (GG*HH + TPB - 1) / TPB;     // covers NN too
    const int gN  = (NN + TPB - 1) / TPB;
    const int gE  = (EE + TPB - 1) / TPB;
    const int gG16 = (NN + 15) / 16;             // 16 nodes per block
    const int gGm = (NN + 127) / 128;
    const int gGg = GG / 128;
    const int gW  = (WTOT + TPB - 1) / TPB;

    const int SMB = 4 * 128 * 36 * 4;   // 73728 B dynamic smem (2-stage A+W)
    cudaFuncSetAttribute(mma_gemm_k< 64,0,false,true ,true >, cudaFuncAttributeMaxDynamicSharedMemorySize, SMB);
    cudaFuncSetAttribute(mma_gemm_k<128,0,false,false,true >, cudaFuncAttributeMaxDynamicSharedMemorySize, SMB);
    cudaFuncSetAttribute(mma_gemm_k<128,3,false,true ,false>, cudaFuncAttributeMaxDynamicSharedMemorySize, SMB);
    cudaFuncSetAttribute(mma_gemm_k<128,1,true ,false,false>, cudaFuncAttributeMaxDynamicSharedMemorySize, SMB);
    cudaFuncSetAttribute(mma_gemm_k<128,2,false,false,true >, cudaFuncAttributeMaxDynamicSharedMemorySize, SMB);
    cudaFuncSetAttribute(head_gemm_k,                         cudaFuncAttributeMaxDynamicSharedMemorySize, SMB);

    // init + CSR build + weight prep
    init_k     <<<gI, TPB>>>(out, hb2);
    csr_hist_k <<<gE, TPB>>>(dst);
    csr_scan1_k<<<NB, TPB>>>();
    csr_scan2_k<<<1,  TPB>>>();
    csr_scan3_k<<<gN, TPB>>>();
    csr_fill_k <<<gE, TPB>>>(src, dst);
    prep_w_k   <<<gW, TPB>>>(in_w, conv_w, pw1, hw1, pw2);

    // Wc = W1a_h @ pw2 (rounded out) ; c2
    mma_gemm_k<128,0,false,false,true><<<1, TPB, SMB>>>(p_wr + WOFF_HW1, 256,
                                                        p_wr + WOFF_PW2T, 128, nullptr, p_wc, 128);
    c2_k<<<1, 128>>>(hw1, pb2, hb1);

    // input projection: h = x @ in_w.T + in_b (rounded)
    mma_gemm_k<64,0,false,true,true><<<gGm, TPB, SMB>>>(x, 64, p_wr + WOFF_INW, 64,
                                                        in_b, p_h, NN);

    // GCN layers: hwsc = (h @ W.T)*dis (fp16) ; h += LN(silu(di*gather + bias))
    for (int l = 0; l < 4; l++) {
        mma_gemm_k<128,1,true,false,false><<<gGm, TPB, SMB>>>(p_h, 128,
                                                              p_wr + WOFF_CONV + (size_t)l*HH*HH, 128,
                                                              nullptr, p_hw, NN);
        if (l < 3) gather_ln_k<false><<<gG16, TPB>>>(conv_b + l*HH, ln_g + l*HH, ln_b + l*HH, batch);
        else       gather_ln_k<true ><<<gG16, TPB>>>(conv_b + l*HH, ln_g + l*HH, ln_b + l*HH, batch);
    }

    // gh = (gsum/cnt) @ W1b.T  (mean-div folded into epilogue, tf32 via CVTA)
    mma_gemm_k<128,3,false,true,false><<<gGg, TPB, SMB>>>(p_gsum, 128,
                                                          p_wr + WOFF_HW1 + 128, 256,
                                                          nullptr, p_gh, GG);

    // physics MLP part 1: t1 = silu(h@pw1.T+pb1) (rounded fp32)
    mma_gemm_k<128,2,false,false,true><<<gGm, TPB, SMB>>>(p_h, 128, p_wr + WOFF_PW1, 128,
                                                          pb1, p_t1, NN);

    // head: out[row] = b2 + silu([h;t1]@[W1a_h;Wc].T + c2 + gh[batch]) . w2
    head_gemm_k<<<gGm, TPB, SMB>>>(hw2, batch, out);
}

// round 12
// speedup vs baseline: 4.0726x; 1.0938x over previous
#include <cuda_runtime.h>
#include <cuda_fp16.h>
#include <cstdint>

#define NN 200000
#define EE 600000
#define GG 8192
#define HH 128
#define NB 196            // scan blocks: 196*1024 >= NN

// weight scratch offsets (floats)
#define WOFF_INW  0
#define WOFF_CONV 8192
#define WOFF_PW1  73728
#define WOFF_HW1  90112
#define WOFF_PW2T 122880
#define WTOT      139264

// ---------------- scratch (device globals: allocation-free) ----------------
__device__ __half g_h  [(size_t)NN*HH];     // residual stream (fp16 = tf32 mantissa)
__device__ __half g_t1 [(size_t)NN*HH];     // phys1 output (fp16)
__device__ __half g_hw [(size_t)NN*HH];     // conv outputs pre-scaled by dis (fp16)
__device__ float  g_dis[NN];
__device__ float  g_gsum[(size_t)GG*HH];
__device__ float  g_cnt[GG];
__device__ float  g_gh [(size_t)GG*HH];
__device__ float  g_wc  [HH*HH];
__device__ float  g_c2  [HH];
__device__ float  g_wr  [WTOT];             // tf32-rounded weights
// CSR
__device__ int g_deg[NN];
__device__ int g_fill[NN];
__device__ int g_rowptr[NN];
__device__ int g_csrc[EE];
__device__ int g_bsum[256];
__device__ int g_boff[256];

// ---------------- small helpers ----------------
__device__ __forceinline__ float4 ld4(const float* p){ return *reinterpret_cast<const float4*>(p); }
__device__ __forceinline__ float siluf(float x){ return x / (1.f + __expf(-x)); }
__device__ __forceinline__ uint32_t f2tf32(float f){
    uint32_t u;
    asm("cvt.rna.tf32.f32 %0, %1;" : "=r"(u) : "f"(f));
    return u;
}
__device__ __forceinline__ float tf32r(float f){ return __uint_as_float(f2tf32(f)); }
__device__ __forceinline__ uint32_t smem_u32(const void* p){
    uint32_t a;
    asm("{ .reg .u64 t; cvta.to.shared.u64 t, %1; cvt.u32.u64 %0, t; }" : "=r"(a) : "l"(p));
    return a;
}
__device__ __forceinline__ void cpa16(uint32_t sa, const void* gp, uint32_t sz){
    asm volatile("cp.async.cg.shared.global [%0], [%1], 16, %2;" :: "r"(sa), "l"(gp), "r"(sz));
}
__device__ __forceinline__ void mma1688(float* d, const uint32_t* a, const uint32_t* b){
    asm volatile("mma.sync.aligned.m16n8k8.row.col.f32.tf32.tf32.f32 "
        "{%0,%1,%2,%3}, {%4,%5,%6,%7}, {%8,%9}, {%0,%1,%2,%3};"
        : "+f"(d[0]), "+f"(d[1]), "+f"(d[2]), "+f"(d[3])
        : "r"(a[0]), "r"(a[1]), "r"(a[2]), "r"(a[3]), "r"(b[0]), "r"(b[1]));
}
// accumulate 8 fp16 (one uint4) into 8 fp32
__device__ __forceinline__ void acc8(float* a, uint4 u){
    float2 f;
    f = __half22float2(*reinterpret_cast<__half2*>(&u.x)); a[0]+=f.x; a[1]+=f.y;
    f = __half22float2(*reinterpret_cast<__half2*>(&u.y)); a[2]+=f.x; a[3]+=f.y;
    f = __half22float2(*reinterpret_cast<__half2*>(&u.z)); a[4]+=f.x; a[5]+=f.y;
    f = __half22float2(*reinterpret_cast<__half2*>(&u.w)); a[6]+=f.x; a[7]+=f.y;
}
__device__ __forceinline__ void unp8(float* a, uint4 u){
    float2 f;
    f = __half22float2(*reinterpret_cast<__half2*>(&u.x)); a[0]=f.x; a[1]=f.y;
    f = __half22float2(*reinterpret_cast<__half2*>(&u.y)); a[2]=f.x; a[3]=f.y;
    f = __half22float2(*reinterpret_cast<__half2*>(&u.z)); a[4]=f.x; a[5]=f.y;
    f = __half22float2(*reinterpret_cast<__half2*>(&u.w)); a[6]=f.x; a[7]=f.y;
}
__device__ __forceinline__ uint4 pk8(const float* v){
    uint4 u;
    *reinterpret_cast<__half2*>(&u.x) = __floats2half2_rn(v[0], v[1]);
    *reinterpret_cast<__half2*>(&u.y) = __floats2half2_rn(v[2], v[3]);
    *reinterpret_cast<__half2*>(&u.z) = __floats2half2_rn(v[4], v[5]);
    *reinterpret_cast<__half2*>(&u.w) = __floats2half2_rn(v[6], v[7]);
    return u;
}

// ---------------- init (deg/fill zero, out=b2, pool zero) ----------------
__global__ void init_k(float* __restrict__ out, const float* __restrict__ b2){
    int i = blockIdx.x*blockDim.x + threadIdx.x;
    if (i < NN) { g_deg[i] = 0; g_fill[i] = 0; out[i] = b2[0]; }
    if (i < GG*HH) g_gsum[i] = 0.f;
    if (i < GG)    g_cnt[i]  = 0.f;
}

// ---------------- CSR build ----------------
__global__ void csr_hist_k(const int* __restrict__ dst){
    int e = blockIdx.x*blockDim.x + threadIdx.x;
    if (e < EE) atomicAdd(&g_deg[dst[e]], 1);
}
__global__ __launch_bounds__(256) void csr_scan1_k(){
    __shared__ int ss[256];
    const int tid = threadIdx.x;
    const int i0  = blockIdx.x*1024 + tid*4;
    int v[4];
#pragma unroll
    for (int q = 0; q < 4; q++) v[q] = (i0+q < NN) ? g_deg[i0+q] : 0;
    int tsum = v[0]+v[1]+v[2]+v[3];
    ss[tid] = tsum; __syncthreads();
#pragma unroll
    for (int off = 1; off < 256; off <<= 1) {
        int t = (tid >= off) ? ss[tid-off] : 0;
        __syncthreads();
        ss[tid] += t;
        __syncthreads();
    }
    if (tid == 255) g_bsum[blockIdx.x] = ss[255];
    int run = ss[tid] - tsum;
#pragma unroll
    for (int q = 0; q < 4; q++) {
        if (i0+q < NN) { g_rowptr[i0+q] = run; run += v[q]; }
    }
}
__global__ __launch_bounds__(256) void csr_scan2_k(){
    __shared__ int ss[256];
    const int tid = threadIdx.x;
    int v = (tid < NB) ? g_bsum[tid] : 0;
    ss[tid] = v; __syncthreads();
#pragma unroll
    for (int off = 1; off < 256; off <<= 1) {
        int t = (tid >= off) ? ss[tid-off] : 0;
        __syncthreads();
        ss[tid] += t;
        __syncthreads();
    }
    if (tid < NB) g_boff[tid] = ss[tid] - v;   // exclusive
}
__global__ void csr_scan3_k(){
    int i = blockIdx.x*blockDim.x + threadIdx.x;
    if (i < NN) {
        g_rowptr[i] += g_boff[i >> 10];
        g_dis[i] = rsqrtf((float)g_deg[i] + 1.0f);
    }
}
__global__ void csr_fill_k(const int* __restrict__ src, const int* __restrict__ dst){
    int e = blockIdx.x*blockDim.x + threadIdx.x;
    if (e < EE) {
        int d = dst[e];
        int pos = g_rowptr[d] + atomicAdd(&g_fill[d], 1);
        g_csrc[pos] = src[e];
    }
}

// ---------------- weight prep: tf32-round all GEMM weights ------------------
__global__ void prep_w_k(const float* __restrict__ in_w, const float* __restrict__ conv_w,
                         const float* __restrict__ pw1, const float* __restrict__ hw1,
                         const float* __restrict__ pw2){
    int i = blockIdx.x*blockDim.x + threadIdx.x;
    if (i < 8192)        g_wr[WOFF_INW  + i] = tf32r(in_w[i]);
    else if (i < 73728)  { int j = i-8192;   g_wr[WOFF_CONV + j] = tf32r(conv_w[j]); }
    else if (i < 90112)  { int j = i-73728;  g_wr[WOFF_PW1  + j] = tf32r(pw1[j]); }
    else if (i < 122880) { int j = i-90112;  g_wr[WOFF_HW1  + j] = tf32r(hw1[j]); }
    else if (i < WTOT)   { int j = i-122880; int r = j>>7, c = j&127;
                           g_wr[WOFF_PW2T + c*HH + r] = tf32r(pw2[j]); }
}
__global__ void c2_k(const float* __restrict__ hw1, const float* __restrict__ pb2,
                     const float* __restrict__ hb1){
    int i = threadIdx.x;
    float s = 0.f;
    for (int k = 0; k < HH; k++) s = fmaf(hw1[i*256 + k], pb2[k], s);
    g_c2[i] = s + hb1[i];
}

// ---------------- TF32 tensor-core GEMM (cp.async 2-stage pipeline) ----------
// out[M,128] = A[M,KT] @ W[128,KT]^T  (A row stride lda elems, W row stride ldw)
// EPI 0: out = acc (+bias) ; EPI 1: conv (out_h = half(acc*dis[row])) ;
// EPI 2: out = silu(acc + bias) ; EPI 3: out = acc / max(g_cnt[row],1)  (pool)
// AH:   A in global is fp16 (exact->fp32 conversion is tf32-valid)
// CVTA: A in global is raw fp32 -> convert fragments to tf32 after LDS
// ROUND: tf32-round fp32 outputs (so they can feed later GEMMs raw)
// OUTH: write fp16 (half2)
template<int KT, int EPI, bool OUTH, bool AH, bool CVTA, bool ROUND>
__global__ __launch_bounds__(256, 2) void mma_gemm_k(
    const void* __restrict__ Av, int lda,
    const float* __restrict__ W, int ldw, const float* __restrict__ bias,
    void* __restrict__ outv, int M)
{
    constexpr int KC = 32, NC = KT / KC;
    constexpr int LDSW = 36;                       // floats
    constexpr int LDSA = AH ? 40 : 36;             // halves or floats
    constexpr int ABYTES = 128 * LDSA * (AH ? 2 : 4);
    constexpr int WBYTES = 128 * LDSW * 4;
    extern __shared__ char smem[];

    const int tid = threadIdx.x, wid = tid >> 5, lid = tid & 31;
    const int wm = wid & 3, wn = wid >> 2;
    const int g  = lid >> 2, t = lid & 3;
    const int brow = blockIdx.x * 128;

    float acc[2][8][4];
#pragma unroll
    for (int mt = 0; mt < 2; mt++)
#pragma unroll
        for (int nt = 0; nt < 8; nt++)
#pragma unroll
            for (int q = 0; q < 4; q++) acc[mt][nt][q] = 0.f;

#define ISSUE(ci) do {                                                          \
        int _st = (ci) & 1;                                                     \
        char* Ad = smem + _st*ABYTES;                                           \
        char* Wd = smem + 2*ABYTES + _st*WBYTES;                                \
        if (AH) {                                                               \
            const __half* Ag = (const __half*)Av;                               \
            _Pragma("unroll")                                                   \
            for (int f = tid; f < 512; f += 256) {                              \
                int row = f >> 2, kq = (f & 3) * 8;                             \
                int gr = brow + row;                                            \
                cpa16(smem_u32(Ad + (row*LDSA + kq)*2),                         \
                      Ag + (size_t)gr*lda + (ci)*KC + kq, (gr < M) ? 16u : 0u); \
            }                                                                   \
        } else {                                                                \
            const float* Ag = (const float*)Av;                                 \
            _Pragma("unroll")                                                   \
            for (int f = tid; f < 1024; f += 256) {                             \
                int row = f >> 3, kq = (f & 7) * 4;                             \
                int gr = brow + row;                                            \
                cpa16(smem_u32(Ad + (row*LDSA + kq)*4),                         \
                      Ag + (size_t)gr*lda + (ci)*KC + kq, (gr < M) ? 16u : 0u); \
            }                                                                   \
        }                                                                       \
        _Pragma("unroll")                                                       \
        for (int f = tid; f < 1024; f += 256) {                                 \
            int n = f >> 3, kq = (f & 7) * 4;                                   \
            cpa16(smem_u32(Wd + (n*LDSW + kq)*4),                               \
                  W + (size_t)n*ldw + (ci)*KC + kq, 16u);                       \
        }                                                                       \
        asm volatile("cp.async.commit_group;");                                 \
    } while(0)

    ISSUE(0);
#pragma unroll
    for (int ci = 0; ci < NC; ci++) {
        if (ci + 1 < NC) { ISSUE(ci + 1); asm volatile("cp.async.wait_group 1;"); }
        else             { asm volatile("cp.async.wait_group 0;"); }
        __syncthreads();
        const char* Ab = smem + (ci & 1)*ABYTES;
        const float* Ws = (const float*)(smem + 2*ABYTES + (ci & 1)*WBYTES);
#pragma unroll
        for (int ks = 0; ks < KC/8; ks++) {
            const int kk = ks*8;
            uint32_t a[2][4], b[8][2];
#pragma unroll
            for (int mt = 0; mt < 2; mt++) {
                if (AH) {
                    const __half* ap = (const __half*)Ab + (wm*32 + mt*16 + g)*LDSA + kk + t;
                    a[mt][0] = __float_as_uint(__half2float(ap[0]));
                    a[mt][1] = __float_as_uint(__half2float(ap[8*LDSA]));
                    a[mt][2] = __float_as_uint(__half2float(ap[4]));
                    a[mt][3] = __float_as_uint(__half2float(ap[8*LDSA + 4]));
                } else {
                    const float* ap = (const float*)Ab + (wm*32 + mt*16 + g)*LDSA + kk + t;
                    a[mt][0] = __float_as_uint(ap[0]);
                    a[mt][1] = __float_as_uint(ap[8*LDSA]);
                    a[mt][2] = __float_as_uint(ap[4]);
                    a[mt][3] = __float_as_uint(ap[8*LDSA + 4]);
                    if (CVTA) {
#pragma unroll
                        for (int q = 0; q < 4; q++) a[mt][q] = f2tf32(__uint_as_float(a[mt][q]));
                    }
                }
            }
#pragma unroll
            for (int nt = 0; nt < 8; nt++) {
                const float* bp = Ws + (wn*64 + nt*8 + g)*LDSW + kk + t;
                b[nt][0] = __float_as_uint(bp[0]);
                b[nt][1] = __float_as_uint(bp[4]);
            }
#pragma unroll
            for (int mt = 0; mt < 2; mt++)
#pragma unroll
                for (int nt = 0; nt < 8; nt++)
                    mma1688(acc[mt][nt], a[mt], b[nt]);
        }
        __syncthreads();
    }
#undef ISSUE

    float*  outf = (float*) outv;
    __half* outh = (__half*)outv;
#pragma unroll
    for (int mt = 0; mt < 2; mt++) {
#pragma unroll
        for (int half = 0; half < 2; half++) {
            int row = brow + wm*32 + mt*16 + g + half*8;
            if (row >= M) continue;
            size_t ro = (size_t)row*HH;
            float dsc = 0.f;
            if (EPI == 1) dsc = g_dis[row];
            if (EPI == 3) dsc = 1.f / fmaxf(g_cnt[row], 1.f);
#pragma unroll
            for (int nt = 0; nt < 8; nt++) {
                int col = wn*64 + nt*8 + t*2;
                float v0 = acc[mt][nt][half*2 + 0];
                float v1 = acc[mt][nt][half*2 + 1];
                if (EPI == 0) {
                    if (bias) { v0 += bias[col]; v1 += bias[col+1]; }
                } else if (EPI == 1 || EPI == 3) {
                    v0 *= dsc; v1 *= dsc;
                } else if (EPI == 2) {
                    v0 = siluf(v0 + bias[col]); v1 = siluf(v1 + bias[col+1]);
                }
                if (ROUND) { v0 = tf32r(v0); v1 = tf32r(v1); }
                if (OUTH) {
                    *reinterpret_cast<__half2*>(outh + ro + col) = __floats2half2_rn(v0, v1);
                } else {
                    *reinterpret_cast<float2*>(outf + ro + col) = make_float2(v0, v1);
                }
            }
        }
    }
}

// ---------------- head GEMM (K=256 split: [h ; t1] fp16, W split: [W1a_h ; Wc])
// hid = silu(acc + c2 + gh[batch]) ; out[row] += hid . w2  (out pre-init to b2)
__global__ __launch_bounds__(256, 2) void head_gemm_k(
    const float* __restrict__ w2, const int* __restrict__ batch,
    float* __restrict__ out)
{
    constexpr int KC = 32, NC = 8;
    constexpr int LDSW = 36, LDSA = 40;
    constexpr int ABYTES = 128 * LDSA * 2;
    constexpr int WBYTES = 128 * LDSW * 4;
    extern __shared__ char smem[];

    const int tid = threadIdx.x, wid = tid >> 5, lid = tid & 31;
    const int wm = wid & 3, wn = wid >> 2;
    const int g  = lid >> 2, t = lid & 3;
    const int brow = blockIdx.x * 128;

    float acc[2][8][4];
#pragma unroll
    for (int mt = 0; mt < 2; mt++)
#pragma unroll
        for (int nt = 0; nt < 8; nt++)
#pragma unroll
            for (int q = 0; q < 4; q++) acc[mt][nt][q] = 0.f;

#define HISSUE(ci) do {                                                         \
        int _st = (ci) & 1;                                                     \
        char* Ad = smem + _st*ABYTES;                                           \
        char* Wd = smem + 2*ABYTES + _st*WBYTES;                                \
        const __half* Ap = ((ci) < 4) ? g_h : g_t1;                             \
        int _ka = ((ci)*KC) & 127;                                              \
        _Pragma("unroll")                                                       \
        for (int f = tid; f < 512; f += 256) {                                  \
            int row = f >> 2, kq = (f & 3) * 8;                                 \
            int gr = brow + row;                                                \
            cpa16(smem_u32(Ad + (row*LDSA + kq)*2),                             \
                  Ap + (size_t)gr*HH + _ka + kq, (gr < NN) ? 16u : 0u);         \
        }                                                                       \
        _Pragma("unroll")                                                       \
        for (int f = tid; f < 1024; f += 256) {                                 \
            int n = f >> 3, kq = (f & 7) * 4;                                   \
            const float* gp = ((ci) < 4)                                        \
                ? g_wr + WOFF_HW1 + (size_t)n*256 + (ci)*KC + kq                \
                : g_wc + (size_t)n*HH + _ka + kq;                               \
            cpa16(smem_u32(Wd + (n*LDSW + kq)*4), gp, 16u);                     \
        }                                                                       \
        asm volatile("cp.async.commit_group;");                                 \
    } while(0)

    HISSUE(0);
#pragma unroll
    for (int ci = 0; ci < NC; ci++) {
        if (ci + 1 < NC) { HISSUE(ci + 1); asm volatile("cp.async.wait_group 1;"); }
        else             { asm volatile("cp.async.wait_group 0;"); }
        __syncthreads();
        const __half* As = (const __half*)(smem + (ci & 1)*ABYTES);
        const float*  Ws = (const float*)(smem + 2*ABYTES + (ci & 1)*WBYTES);
#pragma unroll
        for (int ks = 0; ks < KC/8; ks++) {
            const int kk = ks*8;
            uint32_t a[2][4], b[8][2];
#pragma unroll
            for (int mt = 0; mt < 2; mt++) {
                const __half* ap = As + (wm*32 + mt*16 + g)*LDSA + kk + t;
                a[mt][0] = __float_as_uint(__half2float(ap[0]));
                a[mt][1] = __float_as_uint(__half2float(ap[8*LDSA]));
                a[mt][2] = __float_as_uint(__half2float(ap[4]));
                a[mt][3] = __float_as_uint(__half2float(ap[8*LDSA + 4]));
            }
#pragma unroll
            for (int nt = 0; nt < 8; nt++) {
                const float* bp = Ws + (wn*64 + nt*8 + g)*LDSW + kk + t;
                b[nt][0] = __float_as_uint(bp[0]);
                b[nt][1] = __float_as_uint(bp[4]);
            }
#pragma unroll
            for (int mt = 0; mt < 2; mt++)
#pragma unroll
                for (int nt = 0; nt < 8; nt++)
                    mma1688(acc[mt][nt], a[mt], b[nt]);
        }
        __syncthreads();
    }
#undef HISSUE

#pragma unroll
    for (int mt = 0; mt < 2; mt++) {
#pragma unroll
        for (int half = 0; half < 2; half++) {
            int row = brow + wm*32 + mt*16 + g + half*8;
            float partial = 0.f;
            if (row < NN) {
                const float* ghrow = g_gh + (size_t)batch[row]*HH;
#pragma unroll
                for (int nt = 0; nt < 8; nt++) {
                    int col = wn*64 + nt*8 + t*2;
                    float v0 = siluf(acc[mt][nt][half*2+0] + g_c2[col]   + ghrow[col]);
                    float v1 = siluf(acc[mt][nt][half*2+1] + g_c2[col+1] + ghrow[col+1]);
                    partial = fmaf(v0, w2[col], partial);
                    partial = fmaf(v1, w2[col+1], partial);
                }
            }
            partial += __shfl_xor_sync(0xffffffffu, partial, 1);
            partial += __shfl_xor_sync(0xffffffffu, partial, 2);
            if (t == 0 && row < NN)
                asm volatile("red.global.add.f32 [%0], %1;" :: "l"(out + row), "f"(partial) : "memory");
        }
    }
}

// ---- fused neighbor-gather + silu + LN + residual (+pool) ------------------
// half-warp (16 lanes) per node, 16B fp16 loads; h stored fp16.
template<bool POOL>
__global__ __launch_bounds__(256) void gather_ln_k(const float* __restrict__ bias,
                                                   const float* __restrict__ lng,
                                                   const float* __restrict__ lnb,
                                                   const int* __restrict__ batch)
{
    int node = blockIdx.x * 16 + (threadIdx.x >> 4);
    if (node >= NN) return;
    const int l16 = threadIdx.x & 15;
    const int c0  = l16 * 8;
    const int cnt   = g_deg[node];
    const int start = g_rowptr[node];
    const float di  = g_dis[node];
    const size_t off = (size_t)node*HH + c0;

    float a[8] = {0,0,0,0,0,0,0,0};
    acc8(a, *reinterpret_cast<const uint4*>(g_hw + off));   // self term (already *di)

    int j = 0;
    for (; j + 2 <= cnt; j += 2) {
        int s0 = g_csrc[start + j];
        int s1 = g_csrc[start + j + 1];
        uint4 u0 = *reinterpret_cast<const uint4*>(g_hw + (size_t)s0*HH + c0);
        uint4 u1 = *reinterpret_cast<const uint4*>(g_hw + (size_t)s1*HH + c0);
        acc8(a, u0);
        acc8(a, u1);
    }
    if (j < cnt) {
        int s = g_csrc[start + j];
        acc8(a, *reinterpret_cast<const uint4*>(g_hw + (size_t)s*HH + c0));
    }

    float4 b0 = ld4(bias + c0), b1 = ld4(bias + c0 + 4);
    float s[8];
    s[0] = siluf(fmaf(a[0], di, b0.x)); s[1] = siluf(fmaf(a[1], di, b0.y));
    s[2] = siluf(fmaf(a[2], di, b0.z)); s[3] = siluf(fmaf(a[3], di, b0.w));
    s[4] = siluf(fmaf(a[4], di, b1.x)); s[5] = siluf(fmaf(a[5], di, b1.y));
    s[6] = siluf(fmaf(a[6], di, b1.z)); s[7] = siluf(fmaf(a[7], di, b1.w));

    float sum = 0.f, sq = 0.f;
#pragma unroll
    for (int q = 0; q < 8; q++) { sum += s[q]; sq = fmaf(s[q], s[q], sq); }
#pragma unroll
    for (int o = 1; o < 16; o <<= 1) {
        sum += __shfl_xor_sync(0xffffffffu, sum, o);
        sq  += __shfl_xor_sync(0xffffffffu, sq,  o);
    }
    float mu  = sum * (1.f/128.f);
    float var = sq * (1.f/128.f) - mu*mu;
    float inv = rsqrtf(var + 1e-5f);

    float4 g0 = ld4(lng + c0), g1 = ld4(lng + c0 + 4);
    float4 e0 = ld4(lnb + c0), e1 = ld4(lnb + c0 + 4);
    float hv[8];
    unp8(hv, *reinterpret_cast<const uint4*>(g_h + off));
    hv[0] += (s[0]-mu)*inv*g0.x + e0.x;
    hv[1] += (s[1]-mu)*inv*g0.y + e0.y;
    hv[2] += (s[2]-mu)*inv*g0.z + e0.z;
    hv[3] += (s[3]-mu)*inv*g0.w + e0.w;
    hv[4] += (s[4]-mu)*inv*g1.x + e1.x;
    hv[5] += (s[5]-mu)*inv*g1.y + e1.y;
    hv[6] += (s[6]-mu)*inv*g1.z + e1.z;
    hv[7] += (s[7]-mu)*inv*g1.w + e1.w;
    *reinterpret_cast<uint4*>(g_h + off) = pk8(hv);

    if (POOL) {
        int b = batch[node];
        float* p = g_gsum + (size_t)b*HH + c0;
        asm volatile("red.global.add.v4.f32 [%0], {%1,%2,%3,%4};"
                     :: "l"(p), "f"(hv[0]), "f"(hv[1]), "f"(hv[2]), "f"(hv[3]) : "memory");
        asm volatile("red.global.add.v4.f32 [%0], {%1,%2,%3,%4};"
                     :: "l"(p+4), "f"(hv[4]), "f"(hv[5]), "f"(hv[6]), "f"(hv[7]) : "memory");
        if (l16 == 0) atomicAdd(&g_cnt[b], 1.0f);
    }
}

// ---------------- launch ----------------
extern "C" void kernel_launch(void* const* d_in, const int* in_sizes, int n_in,
                              void* d_out, int out_size)
{
    const float* x      = (const float*)d_in[0];
    const int*   ei     = (const int*)  d_in[1];
    const int*   src    = ei;
    const int*   dst    = ei + EE;
    const int*   batch  = (const int*)  d_in[2];
    const float* in_w   = (const float*)d_in[3];
    const float* in_b   = (const float*)d_in[4];
    const float* conv_w = (const float*)d_in[5];
    const float* conv_b = (const float*)d_in[6];
    const float* ln_g   = (const float*)d_in[7];
    const float* ln_b   = (const float*)d_in[8];
    const float* pw1    = (const float*)d_in[9];
    const float* pb1    = (const float*)d_in[10];
    const float* pw2    = (const float*)d_in[11];
    const float* pb2    = (const float*)d_in[12];
    const float* hw1    = (const float*)d_in[13];
    const float* hb1    = (const float*)d_in[14];
    const float* hw2    = (const float*)d_in[15];
    const float* hb2    = (const float*)d_in[16];
    float* out = (float*)d_out;

    float *p_gsum, *p_gh, *p_wc, *p_wr;
    __half *p_h, *p_t1, *p_hw;
    cudaGetSymbolAddress((void**)&p_h,    g_h);
    cudaGetSymbolAddress((void**)&p_t1,   g_t1);
    cudaGetSymbolAddress((void**)&p_hw,   g_hw);
    cudaGetSymbolAddress((void**)&p_gsum, g_gsum);
    cudaGetSymbolAddress((void**)&p_gh,   g_gh);
    cudaGetSymbolAddress((void**)&p_wc,   g_wc);
    cudaGetSymbolAddress((void**)&p_wr,   g_wr);

    const int TPB = 256;
    const int gI  = (GG*HH + TPB - 1) / TPB;     // covers NN too
    const int gN  = (NN + TPB - 1) / TPB;
    const int gE  = (EE + TPB - 1) / TPB;
    const int gG16 = (NN + 15) / 16;             // 16 nodes per block
    const int gGm = (NN + 127) / 128;
    const int gGg = GG / 128;
    const int gW  = (WTOT + TPB - 1) / TPB;

    const int SMB_F = 4 * 128 * 36 * 4;              // 73728 (fp32 A)
    const int SMB_H = 2*128*40*2 + 2*128*36*4;       // 57344 (fp16 A)
    cudaFuncSetAttribute(mma_gemm_k<128,0,false,false,false,true >, cudaFuncAttributeMaxDynamicSharedMemorySize, SMB_F);
    cudaFuncSetAttribute(mma_gemm_k< 64,0,true ,false,true ,false>, cudaFuncAttributeMaxDynamicSharedMemorySize, SMB_F);
    cudaFuncSetAttribute(mma_gemm_k<128,1,true ,true ,false,false>, cudaFuncAttributeMaxDynamicSharedMemorySize, SMB_H);
    cudaFuncSetAttribute(mma_gemm_k<128,3,false,false,true ,false>, cudaFuncAttributeMaxDynamicSharedMemorySize, SMB_F);
    cudaFuncSetAttribute(mma_gemm_k<128,2,true ,true ,false,false>, cudaFuncAttributeMaxDynamicSharedMemorySize, SMB_H);
    cudaFuncSetAttribute(head_gemm_k,                                cudaFuncAttributeMaxDynamicSharedMemorySize, SMB_H);

    // init + CSR build + weight prep
    init_k     <<<gI, TPB>>>(out, hb2);
    csr_hist_k <<<gE, TPB>>>(dst);
    csr_scan1_k<<<NB, TPB>>>();
    csr_scan2_k<<<1,  TPB>>>();
    csr_scan3_k<<<gN, TPB>>>();
    csr_fill_k <<<gE, TPB>>>(src, dst);
    prep_w_k   <<<gW, TPB>>>(in_w, conv_w, pw1, hw1, pw2);

    // Wc = W1a_h @ pw2 (tf32-rounded out) ; c2
    mma_gemm_k<128,0,false,false,false,true><<<1, TPB, SMB_F>>>(p_wr + WOFF_HW1, 256,
                                                                p_wr + WOFF_PW2T, 128, nullptr, p_wc, 128);
    c2_k<<<1, 128>>>(hw1, pb2, hb1);

    // input projection: h = x @ in_w.T + in_b  (fp16 out)
    mma_gemm_k<64,0,true,false,true,false><<<gGm, TPB, SMB_F>>>(x, 64, p_wr + WOFF_INW, 64,
                                                                in_b, p_h, NN);

    // GCN layers: hwsc = (h @ W.T)*dis (fp16) ; h += LN(silu(di*gather + bias))
    for (int l = 0; l < 4; l++) {
        mma_gemm_k<128,1,true,true,false,false><<<gGm, TPB, SMB_H>>>(p_h, 128,
                                                                     p_wr + WOFF_CONV + (size_t)l*HH*HH, 128,
                                                                     nullptr, p_hw, NN);
        if (l < 3) gather_ln_k<false><<<gG16, TPB>>>(conv_b + l*HH, ln_g + l*HH, ln_b + l*HH, batch);
        else       gather_ln_k<true ><<<gG16, TPB>>>(conv_b + l*HH, ln_g + l*HH, ln_b + l*HH, batch);
    }

    // gh = (gsum/cnt) @ W1b.T  (mean-div folded into epilogue, tf32 via CVTA)
    mma_gemm_k<128,3,false,false,true,false><<<gGg, TPB, SMB_F>>>(p_gsum, 128,
                                                                  p_wr + WOFF_HW1 + 128, 256,
                                                                  nullptr, p_gh, GG);

    // physics MLP part 1: t1 = silu(h@pw1.T+pb1)  (fp16 out)
    mma_gemm_k<128,2,true,true,false,false><<<gGm, TPB, SMB_H>>>(p_h, 128, p_wr + WOFF_PW1, 128,
                                                                 pb1, p_t1, NN);

    // head: out[row] = b2 + silu([h;t1]@[W1a_h;Wc].T + c2 + gh[batch]) . w2
    head_gemm_k<<<gGm, TPB, SMB_H>>>(hw2, batch, out);
}